// round 5
// baseline (speedup 1.0000x reference)
#include <cuda_runtime.h>
#include <cuda_bf16.h>
#include <math.h>
#include <stdint.h>

#define B_SZ   2
#define S_LEN  2048
#define HID_   2048
#define NH     32
#define NKV    8
#define D_HEAD 64
#define M_FEAT 256
#define NC     16
#define CHUNK  128

// ---------------- scratch (device globals; no allocations allowed) ----------------
__device__ float g_q   [B_SZ * S_LEN * NH  * D_HEAD];
__device__ float g_k   [B_SZ * S_LEN * NKV * D_HEAD];
__device__ float g_v   [B_SZ * S_LEN * NKV * D_HEAD];
__device__ float g_phiq[(size_t)B_SZ * NH  * S_LEN * M_FEAT];
__device__ float g_phik[(size_t)B_SZ * NKV * S_LEN * M_FEAT];
__device__ float g_sqq [B_SZ * NH  * S_LEN];
__device__ float g_sqk [B_SZ * NKV * S_LEN];
__device__ float g_stab[B_SZ * NKV];
__device__ float g_kv  [B_SZ * NKV * NC * M_FEAT * D_HEAD];
__device__ float g_kz  [B_SZ * NKV * NC * M_FEAT];
__device__ float g_attn[B_SZ * S_LEN * NH * D_HEAD];

// bf16 hi/lo split buffers (16B-aligned for uint4 access)
#define HS_ELEMS  (B_SZ * S_LEN * HID_)
#define W_ELEMS   ((HID_ + 512 + 512 + HID_) * HID_)
__device__ __align__(16) __nv_bfloat16 g_hsh[HS_ELEMS];
__device__ __align__(16) __nv_bfloat16 g_hsl[HS_ELEMS];
__device__ __align__(16) __nv_bfloat16 g_ath[HS_ELEMS];
__device__ __align__(16) __nv_bfloat16 g_atl[HS_ELEMS];
__device__ __align__(16) __nv_bfloat16 g_wh [W_ELEMS];
__device__ __align__(16) __nv_bfloat16 g_wl [W_ELEMS];

#define WQ_OFF 0
#define WK_OFF (HID_ * HID_)
#define WV_OFF (WK_OFF + 512 * HID_)
#define WO_OFF (WV_OFF + 512 * HID_)

// =================== fp32 -> bf16 hi/lo split (elementwise, x4 vec) ================
__global__ void split_bf16(const float* __restrict__ x, __nv_bfloat16* __restrict__ h,
                           __nv_bfloat16* __restrict__ l, int n4)
{
    int i = blockIdx.x * blockDim.x + threadIdx.x;
    if (i >= n4) return;
    float4 v = ((const float4*)x)[i];
    __nv_bfloat16 h0 = __float2bfloat16(v.x), h1 = __float2bfloat16(v.y);
    __nv_bfloat16 h2 = __float2bfloat16(v.z), h3 = __float2bfloat16(v.w);
    __nv_bfloat162* hp = (__nv_bfloat162*)h;
    hp[2 * i]     = __nv_bfloat162(h0, h1);
    hp[2 * i + 1] = __nv_bfloat162(h2, h3);
    __nv_bfloat162* lp = (__nv_bfloat162*)l;
    lp[2 * i]     = __nv_bfloat162(__float2bfloat16(v.x - __bfloat162float(h0)),
                                   __float2bfloat16(v.y - __bfloat162float(h1)));
    lp[2 * i + 1] = __nv_bfloat162(__float2bfloat16(v.z - __bfloat162float(h2)),
                                   __float2bfloat16(v.w - __bfloat162float(h3)));
}

// ======== bf16 3-pass split GEMM (legacy mma.sync m16n8k16, fragment-order smem) ====
// C(M,N) = A(M,K) @ W(N,K)^T in ~fp32 precision: C = Ah*Bh + Ah*Bl + Al*Bh.
// CTA tile 128m x 128n, BK=32, 256 threads (8 warps: 2m x 4n, each 64m x 32n).

#define GK 2048
#define BK 32
#define NKT (GK / BK)
#define GBUF 32768
#define SMEM_GEMM (2 * GBUF)

__device__ __forceinline__ void mma_bf16(float c[4], const uint32_t a[4], const uint32_t b[2])
{
    asm volatile("mma.sync.aligned.m16n8k16.row.col.f32.bf16.bf16.f32 "
                 "{%0,%1,%2,%3}, {%4,%5,%6,%7}, {%8,%9}, {%0,%1,%2,%3};"
                 : "+f"(c[0]), "+f"(c[1]), "+f"(c[2]), "+f"(c[3])
                 : "r"(a[0]), "r"(a[1]), "r"(a[2]), "r"(a[3]), "r"(b[0]), "r"(b[1]));
}

__global__ __launch_bounds__(256) void gemm_bf16x3(const __nv_bfloat16* __restrict__ Ah,
                                                   const __nv_bfloat16* __restrict__ Al,
                                                   const __nv_bfloat16* __restrict__ Bh,
                                                   const __nv_bfloat16* __restrict__ Bl,
                                                   float* __restrict__ C, int N)
{
    extern __shared__ char smc[];
    const int tid  = threadIdx.x;
    const int warp = tid >> 5, lane = tid & 31;
    const int gid  = lane >> 2, tig = lane & 3;
    const int wm   = (warp & 1) * 64;
    const int wn   = (warp >> 1) * 32;
    const int rowA = blockIdx.y * 128;
    const int rowB = blockIdx.x * 128;

    float acc[4][4][4];
#pragma unroll
    for (int i = 0; i < 4; i++)
#pragma unroll
        for (int j = 0; j < 4; j++)
#pragma unroll
            for (int r = 0; r < 4; r++) acc[i][j][r] = 0.f;

    uint4 pAh[2], pAl[2], pBh[2], pBl[2];

    auto storeA = [&](char* base, int row, int kk8, uint4 v) {
        const int kstep = kk8 >> 1;
        const int reg   = (kk8 & 1) * 2 + ((row >> 3) & 1);
        const int mtile = row >> 4;
        uint32_t off = (uint32_t)((((kstep * 8 + mtile) * 32) + (row & 7) * 4) * 16 + reg * 4);
        *(uint32_t*)(base + off)      = v.x;
        *(uint32_t*)(base + off + 16) = v.y;
        *(uint32_t*)(base + off + 32) = v.z;
        *(uint32_t*)(base + off + 48) = v.w;
    };
    auto storeB = [&](char* base, int n, int kk8, uint4 v) {
        const int kstep = kk8 >> 1;
        const int reg   = kk8 & 1;
        const int ntile = n >> 3;
        uint32_t off = (uint32_t)((((kstep * 16 + ntile) * 32) + (n & 7) * 4) * 8 + reg * 4);
        *(uint32_t*)(base + off)      = v.x;
        *(uint32_t*)(base + off + 8)  = v.y;
        *(uint32_t*)(base + off + 16) = v.z;
        *(uint32_t*)(base + off + 24) = v.w;
    };

    auto prefetch = [&](int kt) {
        const int kb = kt * BK;
#pragma unroll
        for (int t = 0; t < 2; t++) {
            int seg = t * 256 + tid;
            int row = seg >> 2, kk8 = seg & 3;
            pAh[t] = *(const uint4*)(Ah + (size_t)(rowA + row) * GK + kb + kk8 * 8);
            pAl[t] = *(const uint4*)(Al + (size_t)(rowA + row) * GK + kb + kk8 * 8);
            pBh[t] = *(const uint4*)(Bh + (size_t)(rowB + row) * GK + kb + kk8 * 8);
            pBl[t] = *(const uint4*)(Bl + (size_t)(rowB + row) * GK + kb + kk8 * 8);
        }
    };
    auto commit = [&](int b) {   // b = BUFFER index (0/1)
        char* buf = smc + b * GBUF;
#pragma unroll
        for (int t = 0; t < 2; t++) {
            int seg = t * 256 + tid;
            int row = seg >> 2, kk8 = seg & 3;
            storeA(buf,         row, kk8, pAh[t]);
            storeA(buf + 8192,  row, kk8, pAl[t]);
            storeB(buf + 16384, row, kk8, pBh[t]);
            storeB(buf + 24576, row, kk8, pBl[t]);
        }
    };

    prefetch(0);
    commit(0);
    __syncthreads();

    for (int kt = 0; kt < NKT; kt++) {
        const int b = kt & 1;
        if (kt + 1 < NKT) prefetch(kt + 1);

        const char* buf = smc + b * GBUF;
#pragma unroll
        for (int ks = 0; ks < 2; ks++) {
            uint32_t ah[4][4], al[4][4], bh[4][2], bl[4][2];
#pragma unroll
            for (int tm = 0; tm < 4; tm++) {
                const int mtile = (warp & 1) * 4 + tm;
                uint32_t off = (uint32_t)((((ks * 8 + mtile) * 32) + lane) * 16);
                uint4 vh = *(const uint4*)(buf + off);
                ah[tm][0] = vh.x; ah[tm][1] = vh.y; ah[tm][2] = vh.z; ah[tm][3] = vh.w;
                uint4 vl = *(const uint4*)(buf + 8192 + off);
                al[tm][0] = vl.x; al[tm][1] = vl.y; al[tm][2] = vl.z; al[tm][3] = vl.w;
            }
#pragma unroll
            for (int tn = 0; tn < 4; tn++) {
                const int ntile = (warp >> 1) * 4 + tn;
                uint32_t off = (uint32_t)((((ks * 16 + ntile) * 32) + lane) * 8);
                uint2 vh = *(const uint2*)(buf + 16384 + off);
                bh[tn][0] = vh.x; bh[tn][1] = vh.y;
                uint2 vl = *(const uint2*)(buf + 24576 + off);
                bl[tn][0] = vl.x; bl[tn][1] = vl.y;
            }
#pragma unroll
            for (int tm = 0; tm < 4; tm++)
#pragma unroll
                for (int tn = 0; tn < 4; tn++) {
                    mma_bf16(acc[tm][tn], ah[tm], bh[tn]);
                    mma_bf16(acc[tm][tn], ah[tm], bl[tn]);
                    mma_bf16(acc[tm][tn], al[tm], bh[tn]);
                }
        }
        if (kt + 1 < NKT) {
            commit((kt + 1) & 1);   // FIX: buffer index, not chunk index
        }
        __syncthreads();
    }

    // ---- epilogue ----
#pragma unroll
    for (int tm = 0; tm < 4; tm++) {
        const size_t r0 = (size_t)rowA + wm + tm * 16 + gid;
#pragma unroll
        for (int tn = 0; tn < 4; tn++) {
            const int cn = rowB + wn + tn * 8 + tig * 2;
            *(float2*)(C + r0 * N + cn)       = make_float2(acc[tm][tn][0], acc[tm][tn][1]);
            *(float2*)(C + (r0 + 8) * N + cn) = make_float2(acc[tm][tn][2], acc[tm][tn][3]);
        }
    }
}

// ---------------- RoPE, in place. grid = B*S rows, block = nheads*32 ----------------
__global__ void rope_kernel(float* __restrict__ x, const float* __restrict__ cosp,
                            const float* __restrict__ sinp, int nheads)
{
    const int row = blockIdx.x;
    const int h = threadIdx.x >> 5, p = threadIdx.x & 31;
    const float c1 = cosp[row * 64 + p],      s1 = sinp[row * 64 + p];
    const float c2 = cosp[row * 64 + 32 + p], s2 = sinp[row * 64 + 32 + p];
    float* xr = x + ((size_t)row * nheads + h) * 64;
    const float x1 = xr[p], x2 = xr[p + 32];
    xr[p]      = x1 * c1 - x2 * s1;
    xr[p + 32] = x2 * c2 + x1 * s2;
}

__device__ void atomicMaxFloat(float* addr, float val)
{
    int* ia = (int*)addr;
    int old = *ia;
    while (__int_as_float(old) < val) {
        int assumed = old;
        old = atomicCAS(ia, assumed, __float_as_int(val));
        if (old == assumed) break;
    }
}

__global__ void init_stab_kernel(float* stab)
{
    if (threadIdx.x < B_SZ * NKV) stab[threadIdx.x] = -3.4e38f;
}

// ---------------- favor xp: xp = (x*dn) @ proj^T, also sq and (for k) head max ----
__global__ __launch_bounds__(256) void favor_xp(const float* __restrict__ x,
                                                const float* __restrict__ proj,
                                                float* __restrict__ xp,
                                                float* __restrict__ sq,
                                                float* __restrict__ stab,
                                                int nheads)
{
    __shared__ float As[32 * 68];
    __shared__ float Bs[16][256];
    __shared__ float red[256];
    const float DN = 0.35355339059327373f;
    const int s0 = blockIdx.x * 32, h = blockIdx.y, b = blockIdx.z;
    const int tid = threadIdx.x;

#pragma unroll
    for (int r = 0; r < 2; r++) {
        int l = tid + r * 256;
        int tok = l >> 4, q4 = (l & 15) << 2;
        float4 vv = *(const float4*)(x + ((size_t)(b * S_LEN + s0 + tok) * nheads + h) * 64 + q4);
        As[tok * 68 + q4 + 0] = vv.x * DN;
        As[tok * 68 + q4 + 1] = vv.y * DN;
        As[tok * 68 + q4 + 2] = vv.z * DN;
        As[tok * 68 + q4 + 3] = vv.w * DN;
    }
    __syncthreads();
    if (tid < 32) {
        float ssum = 0.f;
#pragma unroll
        for (int d = 0; d < 64; d++) { float vv = As[tid * 68 + d]; ssum += vv * vv; }
        sq[((size_t)(b * nheads + h)) * S_LEN + s0 + tid] = 0.5f * ssum;
    }

    const int tg = tid >> 5, mg = tid & 31;
    float acc[4][8];
#pragma unroll
    for (int i = 0; i < 4; i++)
#pragma unroll
        for (int j = 0; j < 8; j++) acc[i][j] = 0.f;

    for (int k0 = 0; k0 < 64; k0 += 16) {
#pragma unroll
        for (int j = 0; j < 4; j++) {
            float4 p = *(const float4*)(proj + tid * 64 + k0 + j * 4);
            Bs[j * 4 + 0][tid] = p.x; Bs[j * 4 + 1][tid] = p.y;
            Bs[j * 4 + 2][tid] = p.z; Bs[j * 4 + 3][tid] = p.w;
        }
        __syncthreads();
#pragma unroll
        for (int kk = 0; kk < 16; kk++) {
            float a[4];
#pragma unroll
            for (int i = 0; i < 4; i++) a[i] = As[(tg * 4 + i) * 68 + k0 + kk];
            float bb[8];
            *(float4*)&bb[0] = *(const float4*)&Bs[kk][mg * 8];
            *(float4*)&bb[4] = *(const float4*)&Bs[kk][mg * 8 + 4];
#pragma unroll
            for (int i = 0; i < 4; i++)
#pragma unroll
                for (int j = 0; j < 8; j++) acc[i][j] += a[i] * bb[j];
        }
        __syncthreads();
    }

    float mx = -3.4e38f;
    const size_t rowbase = (size_t)(b * nheads + h) * S_LEN + s0;
#pragma unroll
    for (int i = 0; i < 4; i++) {
        *(float4*)(xp + (rowbase + tg * 4 + i) * M_FEAT + mg * 8) =
            make_float4(acc[i][0], acc[i][1], acc[i][2], acc[i][3]);
        *(float4*)(xp + (rowbase + tg * 4 + i) * M_FEAT + mg * 8 + 4) =
            make_float4(acc[i][4], acc[i][5], acc[i][6], acc[i][7]);
        if (stab) {
#pragma unroll
            for (int j = 0; j < 8; j++) mx = fmaxf(mx, acc[i][j]);
        }
    }
    if (stab) {
        red[tid] = mx;
        __syncthreads();
        for (int st = 128; st > 0; st >>= 1) {
            if (tid < st) red[tid] = fmaxf(red[tid], red[tid + st]);
            __syncthreads();
        }
        if (tid == 0) atomicMaxFloat(&stab[b * nheads + h], red[0]);
    }
}

// ---------------- finalize phi in place ------
__global__ void favor_fin(float* __restrict__ xp, const float* __restrict__ sq,
                          const float* __restrict__ stab, int is_query, int nrows)
{
    const int warp = (blockIdx.x * blockDim.x + threadIdx.x) >> 5;
    const int lane = threadIdx.x & 31;
    if (warp >= nrows) return;
    float* row = xp + (size_t)warp * M_FEAT;
    float vals[8];
#pragma unroll
    for (int k = 0; k < 8; k++) vals[k] = row[lane + k * 32];
    float mx;
    if (is_query) {
        mx = vals[0];
#pragma unroll
        for (int k = 1; k < 8; k++) mx = fmaxf(mx, vals[k]);
#pragma unroll
        for (int o = 16; o > 0; o >>= 1) mx = fmaxf(mx, __shfl_xor_sync(0xffffffffu, mx, o));
    } else {
        mx = stab[warp / S_LEN];
    }
    const float sqv = sq[warp];
#pragma unroll
    for (int k = 0; k < 8; k++)
        row[lane + k * 32] = (expf(vals[k] - sqv - mx) + 1e-6f) * 0.0625f;
}

// ---------------- per-chunk kv (M x D) and kz (M). grid (NC, NKV, B) ---------------
__global__ __launch_bounds__(256) void kv_chunk(const float* __restrict__ phik,
                                                const float* __restrict__ v,
                                                float* __restrict__ kv,
                                                float* __restrict__ kz)
{
    __shared__ float ps[16][256];
    __shared__ float vs[16][64];
    const int c = blockIdx.x, h = blockIdx.y, b = blockIdx.z;
    const int tid = threadIdx.x;
    float acc[64];
#pragma unroll
    for (int d = 0; d < 64; d++) acc[d] = 0.f;
    float accz = 0.f;
    const size_t prow = (size_t)(b * NKV + h) * S_LEN + c * CHUNK;
    const size_t vrow = (size_t)b * S_LEN + c * CHUNK;

    for (int i0 = 0; i0 < CHUNK; i0 += 16) {
#pragma unroll
        for (int ii = 0; ii < 16; ii++)
            ps[ii][tid] = phik[(prow + i0 + ii) * M_FEAT + tid];
#pragma unroll
        for (int j = 0; j < 4; j++) {
            int l = tid + j * 256;
            int ii = l >> 6, d = l & 63;
            vs[ii][d] = v[(vrow + i0 + ii) * (NKV * D_HEAD) + h * D_HEAD + d];
        }
        __syncthreads();
#pragma unroll
        for (int ii = 0; ii < 16; ii++) {
            float a = ps[ii][tid];
            accz += a;
#pragma unroll
            for (int d4 = 0; d4 < 64; d4 += 4) {
                float4 vv = *(const float4*)&vs[ii][d4];
                acc[d4 + 0] += a * vv.x; acc[d4 + 1] += a * vv.y;
                acc[d4 + 2] += a * vv.z; acc[d4 + 3] += a * vv.w;
            }
        }
        __syncthreads();
    }
    const size_t ob = (((size_t)(b * NKV + h) * NC + c) * M_FEAT + tid) * D_HEAD;
#pragma unroll
    for (int d4 = 0; d4 < 64; d4 += 4)
        *(float4*)(kv + ob + d4) = make_float4(acc[d4], acc[d4 + 1], acc[d4 + 2], acc[d4 + 3]);
    kz[((size_t)(b * NKV + h) * NC + c) * M_FEAT + tid] = accz;
}

// ---------------- exclusive prefix over chunk axis, in place ----------------------
__global__ void cumsum_k(float* __restrict__ kv, float* __restrict__ kz)
{
    const int tid = blockIdx.x * blockDim.x + threadIdx.x;
    const int KVSZ = M_FEAT * D_HEAD;
    if (tid < B_SZ * NKV * KVSZ) {
        int bh = tid / KVSZ, md = tid % KVSZ;
        float run = 0.f;
        for (int c = 0; c < NC; c++) {
            size_t idx = ((size_t)bh * NC + c) * KVSZ + md;
            float t = kv[idx]; kv[idx] = run; run += t;
        }
    } else {
        int t2 = tid - B_SZ * NKV * KVSZ;
        if (t2 < B_SZ * NKV * M_FEAT) {
            int bh = t2 / M_FEAT, m = t2 % M_FEAT;
            float run = 0.f;
            for (int c = 0; c < NC; c++) {
                size_t idx = ((size_t)bh * NC + c) * M_FEAT + m;
                float tz = kz[idx]; kz[idx] = run; run += tz;
            }
        }
    }
}

// ---------------- chunked causal linear attention. grid (NC, NH, B) ---------------
__global__ __launch_bounds__(256) void attn_chunk(
    const float* __restrict__ phiq, const float* __restrict__ phik,
    const float* __restrict__ v, const float* __restrict__ kvpre,
    const float* __restrict__ kzpre, float* __restrict__ outp)
{
    extern __shared__ float sm[];
    float* Ss  = sm;
    float* Ast = sm + 128 * 129;
    float* Bst = Ast + 16 * 128;
    float* Vs  = Bst + 16 * 128;
    float* KZs = Vs + 16 * 64;
    float* Zs  = KZs + 16;
    float* Z2  = Zs + 128;

    const int c = blockIdx.x, h = blockIdx.y, b = blockIdx.z;
    const int kvh = h >> 2;
    const int tid = threadIdx.x;
    const int tx = tid & 15, ty = tid >> 4;

    const size_t qbase  = (size_t)(b * NH + h) * S_LEN + c * CHUNK;
    const size_t kbase  = (size_t)(b * NKV + kvh) * S_LEN + c * CHUNK;
    const size_t vbase  = (size_t)b * S_LEN + c * CHUNK;
    const size_t kvbase = ((size_t)(b * NKV + kvh) * NC + c) * (size_t)M_FEAT * D_HEAD;
    const size_t kzbase = ((size_t)(b * NKV + kvh) * NC + c) * M_FEAT;

    const int cr = tid >> 1, k8 = (tid & 1) * 8;

    {
        float acc[8][8];
#pragma unroll
        for (int i = 0; i < 8; i++)
#pragma unroll
            for (int j = 0; j < 8; j++) acc[i][j] = 0.f;

        for (int m0 = 0; m0 < M_FEAT; m0 += 16) {
#pragma unroll
            for (int j = 0; j < 8; j += 4) {
                float4 qv = *(const float4*)(phiq + (qbase + cr) * M_FEAT + m0 + k8 + j);
                Ast[(k8 + j + 0) * 128 + cr] = qv.x;
                Ast[(k8 + j + 1) * 128 + cr] = qv.y;
                Ast[(k8 + j + 2) * 128 + cr] = qv.z;
                Ast[(k8 + j + 3) * 128 + cr] = qv.w;
                float4 kk4 = *(const float4*)(phik + (kbase + cr) * M_FEAT + m0 + k8 + j);
                Bst[(k8 + j + 0) * 128 + cr] = kk4.x;
                Bst[(k8 + j + 1) * 128 + cr] = kk4.y;
                Bst[(k8 + j + 2) * 128 + cr] = kk4.z;
                Bst[(k8 + j + 3) * 128 + cr] = kk4.w;
            }
            __syncthreads();
#pragma unroll
            for (int kk = 0; kk < 16; kk++) {
                float a[8], bb[8];
                *(float4*)&a[0]  = *(const float4*)&Ast[kk * 128 + ty * 8];
                *(float4*)&a[4]  = *(const float4*)&Ast[kk * 128 + ty * 8 + 4];
                *(float4*)&bb[0] = *(const float4*)&Bst[kk * 128 + tx * 8];
                *(float4*)&bb[4] = *(const float4*)&Bst[kk * 128 + tx * 8 + 4];
#pragma unroll
                for (int i = 0; i < 8; i++)
#pragma unroll
                    for (int j = 0; j < 8; j++) acc[i][j] += a[i] * bb[j];
            }
            __syncthreads();
        }
#pragma unroll
        for (int i = 0; i < 8; i++) {
            int r = ty * 8 + i;
#pragma unroll
            for (int j = 0; j < 8; j++) {
                int t = tx * 8 + j;
                Ss[r * 129 + t] = (t <= r) ? acc[i][j] : 0.f;
            }
        }
    }
    __syncthreads();

    {
        int r = tid >> 1, hf = tid & 1;
        float zz = 0.f;
#pragma unroll
        for (int t = 0; t < 64; t++) zz += Ss[r * 129 + hf * 64 + t];
        Z2[tid] = zz;
    }

    float acc2[8][4];
#pragma unroll
    for (int i = 0; i < 8; i++)
#pragma unroll
        for (int j = 0; j < 4; j++) acc2[i][j] = 0.f;
    float zreg = 0.f;

    for (int m0 = 0; m0 < M_FEAT; m0 += 16) {
#pragma unroll
        for (int j = 0; j < 8; j += 4) {
            float4 qv = *(const float4*)(phiq + (qbase + cr) * M_FEAT + m0 + k8 + j);
            Ast[(k8 + j + 0) * 128 + cr] = qv.x;
            Ast[(k8 + j + 1) * 128 + cr] = qv.y;
            Ast[(k8 + j + 2) * 128 + cr] = qv.z;
            Ast[(k8 + j + 3) * 128 + cr] = qv.w;
        }
        {
            float4 kvv = *(const float4*)(kvpre + kvbase + (size_t)(m0 + (tid >> 4)) * 64 + (tid & 15) * 4);
            *(float4*)&Vs[(tid >> 4) * 64 + (tid & 15) * 4] = kvv;
        }
        if (tid < 16) KZs[tid] = kzpre[kzbase + m0 + tid];
        __syncthreads();
#pragma unroll
        for (int kk = 0; kk < 16; kk++) {
            float a[8];
            *(float4*)&a[0] = *(const float4*)&Ast[kk * 128 + ty * 8];
            *(float4*)&a[4] = *(const float4*)&Ast[kk * 128 + ty * 8 + 4];
            float bb[4];
            *(float4*)&bb[0] = *(const float4*)&Vs[kk * 64 + tx * 4];
#pragma unroll
            for (int i = 0; i < 8; i++)
#pragma unroll
                for (int j = 0; j < 4; j++) acc2[i][j] += a[i] * bb[j];
        }
        if (tid < 128) {
#pragma unroll
            for (int kk = 0; kk < 16; kk++)
                zreg += Ast[kk * 128 + tid] * KZs[kk];
        }
        __syncthreads();
    }
    if (tid < 128) Zs[tid] = zreg;
    __syncthreads();
    if (tid < 128) Zs[tid] += Z2[2 * tid] + Z2[2 * tid + 1];
    __syncthreads();

    for (int t0 = 0; t0 < CHUNK; t0 += 16) {
        float4 vv = *(const float4*)(v + (vbase + t0 + (tid >> 4)) * (NKV * D_HEAD) + kvh * D_HEAD + (tid & 15) * 4);
        *(float4*)&Vs[(tid >> 4) * 64 + (tid & 15) * 4] = vv;
        __syncthreads();
#pragma unroll
        for (int kk = 0; kk < 16; kk++) {
            float a[8];
#pragma unroll
            for (int i = 0; i < 8; i++) a[i] = Ss[(ty * 8 + i) * 129 + t0 + kk];
            float bb[4];
            *(float4*)&bb[0] = *(const float4*)&Vs[kk * 64 + tx * 4];
#pragma unroll
            for (int i = 0; i < 8; i++)
#pragma unroll
                for (int j = 0; j < 4; j++) acc2[i][j] += a[i] * bb[j];
        }
        __syncthreads();
    }

#pragma unroll
    for (int i = 0; i < 8; i++) {
        int r = ty * 8 + i;
        float dnm = 1.f / (Zs[r] + 1e-6f);
        float4 o = make_float4(acc2[i][0] * dnm, acc2[i][1] * dnm,
                               acc2[i][2] * dnm, acc2[i][3] * dnm);
        *(float4*)(outp + ((size_t)b * S_LEN + c * CHUNK + r) * (NH * D_HEAD) + h * D_HEAD + tx * 4) = o;
    }
}

// ----------------------------------- launch ---------------------------------------
extern "C" void kernel_launch(void* const* d_in, const int* in_sizes, int n_in,
                              void* d_out, int out_size)
{
    const float* hs   = (const float*)d_in[0];
    const float* cosp = (const float*)d_in[1];
    const float* sinp = (const float*)d_in[2];
    const float* Wq   = (const float*)d_in[3];
    const float* Wk   = (const float*)d_in[4];
    const float* Wv   = (const float*)d_in[5];
    const float* Wo   = (const float*)d_in[6];
    const float* proj = (const float*)d_in[7];
    float* out = (float*)d_out;

    float *qp, *kp, *vp, *phiqp, *phikp, *sqqp, *sqkp, *stabp, *kvp, *kzp, *attnp;
    cudaGetSymbolAddress((void**)&qp,    g_q);
    cudaGetSymbolAddress((void**)&kp,    g_k);
    cudaGetSymbolAddress((void**)&vp,    g_v);
    cudaGetSymbolAddress((void**)&phiqp, g_phiq);
    cudaGetSymbolAddress((void**)&phikp, g_phik);
    cudaGetSymbolAddress((void**)&sqqp,  g_sqq);
    cudaGetSymbolAddress((void**)&sqkp,  g_sqk);
    cudaGetSymbolAddress((void**)&stabp, g_stab);
    cudaGetSymbolAddress((void**)&kvp,   g_kv);
    cudaGetSymbolAddress((void**)&kzp,   g_kz);
    cudaGetSymbolAddress((void**)&attnp, g_attn);

    __nv_bfloat16 *hsh, *hsl, *ath, *atl, *wh, *wl;
    cudaGetSymbolAddress((void**)&hsh, g_hsh);
    cudaGetSymbolAddress((void**)&hsl, g_hsl);
    cudaGetSymbolAddress((void**)&ath, g_ath);
    cudaGetSymbolAddress((void**)&atl, g_atl);
    cudaGetSymbolAddress((void**)&wh,  g_wh);
    cudaGetSymbolAddress((void**)&wl,  g_wl);

    const int smem_attn = (128 * 129 + 2 * 16 * 128 + 16 * 64 + 16 + 128 + 256) * 4;
    cudaFuncSetAttribute(attn_chunk, cudaFuncAttributeMaxDynamicSharedMemorySize, smem_attn);
    cudaFuncSetAttribute(gemm_bf16x3, cudaFuncAttributeMaxDynamicSharedMemorySize, SMEM_GEMM);

    // ---- splits: hs + all weights ----
    split_bf16<<<(HS_ELEMS / 4 + 255) / 256, 256>>>(hs, hsh, hsl, HS_ELEMS / 4);
    split_bf16<<<(HID_ * HID_ / 4 + 255) / 256, 256>>>(Wq, wh + WQ_OFF, wl + WQ_OFF, HID_ * HID_ / 4);
    split_bf16<<<(512 * HID_ / 4 + 255) / 256, 256>>>(Wk, wh + WK_OFF, wl + WK_OFF, 512 * HID_ / 4);
    split_bf16<<<(512 * HID_ / 4 + 255) / 256, 256>>>(Wv, wh + WV_OFF, wl + WV_OFF, 512 * HID_ / 4);
    split_bf16<<<(HID_ * HID_ / 4 + 255) / 256, 256>>>(Wo, wh + WO_OFF, wl + WO_OFF, HID_ * HID_ / 4);

    // ---- QKV projections (bf16 split, tensor cores) ----
    gemm_bf16x3<<<dim3(16, 32), 256, SMEM_GEMM>>>(hsh, hsl, wh + WQ_OFF, wl + WQ_OFF, qp, 2048);
    gemm_bf16x3<<<dim3(4, 32), 256, SMEM_GEMM>>>(hsh, hsl, wh + WK_OFF, wl + WK_OFF, kp, 512);
    gemm_bf16x3<<<dim3(4, 32), 256, SMEM_GEMM>>>(hsh, hsl, wh + WV_OFF, wl + WV_OFF, vp, 512);

    // ---- RoPE ----
    rope_kernel<<<B_SZ * S_LEN, NH * 32>>>(qp, cosp, sinp, NH);
    rope_kernel<<<B_SZ * S_LEN, NKV * 32>>>(kp, cosp, sinp, NKV);

    // ---- favor features ----
    init_stab_kernel<<<1, 32>>>(stabp);
    favor_xp<<<dim3(S_LEN / 32, NH, B_SZ), 256>>>(qp, proj, phiqp, sqqp, nullptr, NH);
    favor_xp<<<dim3(S_LEN / 32, NKV, B_SZ), 256>>>(kp, proj, phikp, sqkp, stabp, NKV);
    favor_fin<<<(B_SZ * NH * S_LEN) / 8, 256>>>(phiqp, sqqp, nullptr, 1, B_SZ * NH * S_LEN);
    favor_fin<<<(B_SZ * NKV * S_LEN) / 8, 256>>>(phikp, sqkp, stabp, 0, B_SZ * NKV * S_LEN);

    // ---- chunked linear attention ----
    kv_chunk<<<dim3(NC, NKV, B_SZ), 256>>>(phikp, vp, kvp, kzp);
    cumsum_k<<<(B_SZ * NKV * (M_FEAT * D_HEAD + M_FEAT) + 255) / 256, 256>>>(kvp, kzp);
    attn_chunk<<<dim3(NC, NH, B_SZ), 256, smem_attn>>>(phiqp, phikp, vp, kvp, kzp, attnp);

    // ---- output projection (bf16 split, tensor cores) ----
    split_bf16<<<(HS_ELEMS / 4 + 255) / 256, 256>>>(attnp, ath, atl, HS_ELEMS / 4);
    gemm_bf16x3<<<dim3(16, 32), 256, SMEM_GEMM>>>(ath, atl, wh + WO_OFF, wl + WO_OFF, out, 2048);
}

// round 6
// speedup vs baseline: 1.3374x; 1.3374x over previous
#include <cuda_runtime.h>
#include <cuda_bf16.h>
#include <math.h>
#include <stdint.h>

#define B_SZ   2
#define S_LEN  2048
#define HID_   2048
#define NH     32
#define NKV    8
#define D_HEAD 64
#define M_FEAT 256
#define NC     16
#define CHUNK  128

// ---------------- scratch (device globals; no allocations allowed) ----------------
__device__ float g_q   [B_SZ * S_LEN * NH  * D_HEAD];
__device__ float g_k   [B_SZ * S_LEN * NKV * D_HEAD];
__device__ float g_v   [B_SZ * S_LEN * NKV * D_HEAD];
__device__ float g_phiq[(size_t)B_SZ * NH  * S_LEN * M_FEAT];
__device__ float g_phik[(size_t)B_SZ * NKV * S_LEN * M_FEAT];
__device__ float g_sqq [B_SZ * NH  * S_LEN];
__device__ float g_sqk [B_SZ * NKV * S_LEN];
__device__ float g_stab[B_SZ * NKV];
__device__ float g_kv  [B_SZ * NKV * NC * M_FEAT * D_HEAD];
__device__ float g_kz  [B_SZ * NKV * NC * M_FEAT];
__device__ float g_attn[B_SZ * S_LEN * NH * D_HEAD];

// bf16 hi/lo split buffers (16B-aligned for uint4 access)
#define HS_ELEMS  (B_SZ * S_LEN * HID_)
#define W_ELEMS   ((HID_ + 512 + 512 + HID_) * HID_)
__device__ __align__(16) __nv_bfloat16 g_hsh[HS_ELEMS];
__device__ __align__(16) __nv_bfloat16 g_hsl[HS_ELEMS];
__device__ __align__(16) __nv_bfloat16 g_ath[HS_ELEMS];
__device__ __align__(16) __nv_bfloat16 g_atl[HS_ELEMS];
__device__ __align__(16) __nv_bfloat16 g_wh [W_ELEMS];
__device__ __align__(16) __nv_bfloat16 g_wl [W_ELEMS];

#define WQ_OFF 0
#define WK_OFF (HID_ * HID_)
#define WV_OFF (WK_OFF + 512 * HID_)
#define WO_OFF (WV_OFF + 512 * HID_)

// =================== fp32 -> bf16 hi/lo split (elementwise, x4 vec) ================
__global__ void split_bf16(const float* __restrict__ x, __nv_bfloat16* __restrict__ h,
                           __nv_bfloat16* __restrict__ l, int n4)
{
    int i = blockIdx.x * blockDim.x + threadIdx.x;
    if (i >= n4) return;
    float4 v = ((const float4*)x)[i];
    __nv_bfloat16 h0 = __float2bfloat16(v.x), h1 = __float2bfloat16(v.y);
    __nv_bfloat16 h2 = __float2bfloat16(v.z), h3 = __float2bfloat16(v.w);
    __nv_bfloat162* hp = (__nv_bfloat162*)h;
    hp[2 * i]     = __nv_bfloat162(h0, h1);
    hp[2 * i + 1] = __nv_bfloat162(h2, h3);
    __nv_bfloat162* lp = (__nv_bfloat162*)l;
    lp[2 * i]     = __nv_bfloat162(__float2bfloat16(v.x - __bfloat162float(h0)),
                                   __float2bfloat16(v.y - __bfloat162float(h1)));
    lp[2 * i + 1] = __nv_bfloat162(__float2bfloat16(v.z - __bfloat162float(h2)),
                                   __float2bfloat16(v.w - __bfloat162float(h3)));
}

// ======== bf16 3-pass split GEMM v2: ldmatrix + swizzled smem, m16n8k16 ============
// C(M,N) = A(M,K) @ W(N,K)^T, C = Ah*Bh + Ah*Bl + Al*Bh (fp32 accum).
// CTA 128m x 128n, BK=32, 256 threads (8 warps: 2m x 4n; warp = 64m x 32n).
// smem buffer (32KB): Ah[0,8K) Al[8K,16K) Bh[16K,24K) Bl[24K,32K); double buffered.
// Each section: 128 rows x 64B, slot-swizzled: addr(row,slot)=row*64+((slot^((row>>1)&3))*16)

#define GK 2048
#define BK 32
#define NKT (GK / BK)
#define GBUF 32768
#define SMEM_GEMM (2 * GBUF)

__device__ __forceinline__ uint32_t smem_u32g(const void* p)
{
    uint32_t a;
    asm("{ .reg .u64 t; cvta.to.shared.u64 t, %1; cvt.u32.u64 %0, t; }" : "=r"(a) : "l"(p));
    return a;
}

#define LDSM4(r, a) \
    asm volatile("ldmatrix.sync.aligned.m8n8.x4.shared.b16 {%0,%1,%2,%3}, [%4];" \
                 : "=r"((r)[0]), "=r"((r)[1]), "=r"((r)[2]), "=r"((r)[3]) : "r"(a))

__device__ __forceinline__ void mma_bf16(float c[4], const uint32_t a[4], const uint32_t b[2])
{
    asm volatile("mma.sync.aligned.m16n8k16.row.col.f32.bf16.bf16.f32 "
                 "{%0,%1,%2,%3}, {%4,%5,%6,%7}, {%8,%9}, {%0,%1,%2,%3};"
                 : "+f"(c[0]), "+f"(c[1]), "+f"(c[2]), "+f"(c[3])
                 : "r"(a[0]), "r"(a[1]), "r"(a[2]), "r"(a[3]), "r"(b[0]), "r"(b[1]));
}

__global__ __launch_bounds__(256, 1) void gemm_bf16x3(const __nv_bfloat16* __restrict__ Ah,
                                                      const __nv_bfloat16* __restrict__ Al,
                                                      const __nv_bfloat16* __restrict__ Bh,
                                                      const __nv_bfloat16* __restrict__ Bl,
                                                      float* __restrict__ C, int N)
{
    extern __shared__ char smc[];
    const uint32_t sb = smem_u32g(smc);
    const int tid  = threadIdx.x;
    const int warp = tid >> 5, lane = tid & 31;
    const int gid  = lane >> 2, tig = lane & 3;
    const int wm   = (warp & 1) * 64;
    const int wn   = (warp >> 1) * 32;
    const int rowA = blockIdx.y * 128;
    const int rowB = blockIdx.x * 128;

    // staging: seg -> (row = seg>>2, slot = seg&3); swizzled store offset
    const int st_row  = tid >> 2;            // rows 0..63 (i=0), 64..127 (i=1)
    const int st_slot = tid & 3;
    const uint32_t st_off0 = (uint32_t)(st_row * 64 + ((st_slot ^ ((st_row >> 1) & 3)) * 16));
    const int st_row1 = st_row + 64;
    const uint32_t st_off1 = (uint32_t)(st_row1 * 64 + ((st_slot ^ ((st_row1 >> 1) & 3)) * 16));

    // ldmatrix per-thread address pieces
    const int swm   = ((lane & 7) >> 1) & 3;                  // swizzle mask (A and B alike)
    const int rlocA = (lane & 7) + (((lane >> 3) & 1) << 3);  // row-in-16 for A x4
    const int shA   = lane >> 4;                              // k-half select for A
    const int rlocB = (lane & 7) + ((lane >> 4) << 3);        // row-in-16 for B x4 (2 ntiles)
    const int shB   = (lane >> 3) & 1;                        // k-half select for B

    float acc[4][4][4];
#pragma unroll
    for (int i = 0; i < 4; i++)
#pragma unroll
        for (int j = 0; j < 4; j++)
#pragma unroll
            for (int r = 0; r < 4; r++) acc[i][j][r] = 0.f;

    uint4 pAh[2], pAl[2], pBh[2], pBl[2];

    auto prefetch = [&](int kt) {
        const int kb = kt * BK;
        pAh[0] = *(const uint4*)(Ah + (size_t)(rowA + st_row)  * GK + kb + st_slot * 8);
        pAh[1] = *(const uint4*)(Ah + (size_t)(rowA + st_row1) * GK + kb + st_slot * 8);
        pAl[0] = *(const uint4*)(Al + (size_t)(rowA + st_row)  * GK + kb + st_slot * 8);
        pAl[1] = *(const uint4*)(Al + (size_t)(rowA + st_row1) * GK + kb + st_slot * 8);
        pBh[0] = *(const uint4*)(Bh + (size_t)(rowB + st_row)  * GK + kb + st_slot * 8);
        pBh[1] = *(const uint4*)(Bh + (size_t)(rowB + st_row1) * GK + kb + st_slot * 8);
        pBl[0] = *(const uint4*)(Bl + (size_t)(rowB + st_row)  * GK + kb + st_slot * 8);
        pBl[1] = *(const uint4*)(Bl + (size_t)(rowB + st_row1) * GK + kb + st_slot * 8);
    };
    auto commit = [&](int b) {
        char* buf = smc + b * GBUF;
        *(uint4*)(buf + st_off0)         = pAh[0];
        *(uint4*)(buf + st_off1)         = pAh[1];
        *(uint4*)(buf + 8192  + st_off0) = pAl[0];
        *(uint4*)(buf + 8192  + st_off1) = pAl[1];
        *(uint4*)(buf + 16384 + st_off0) = pBh[0];
        *(uint4*)(buf + 16384 + st_off1) = pBh[1];
        *(uint4*)(buf + 24576 + st_off0) = pBl[0];
        *(uint4*)(buf + 24576 + st_off1) = pBl[1];
    };

    prefetch(0);
    commit(0);
    __syncthreads();

    for (int kt = 0; kt < NKT; kt++) {
        const uint32_t base = sb + (kt & 1) * GBUF;
        if (kt + 1 < NKT) prefetch(kt + 1);

#pragma unroll
        for (int kb = 0; kb < 2; kb++) {
            // ---- A fragments: 4 mtiles x (hi, lo), one LDSM.x4 each ----
            uint32_t ah[4][4], al[4][4];
#pragma unroll
            for (int tm = 0; tm < 4; tm++) {
                const int r = wm + tm * 16 + rlocA;
                const uint32_t off = (uint32_t)(r * 64 + (((2 * kb + shA) ^ swm) * 16));
                LDSM4(ah[tm], base + off);
                LDSM4(al[tm], base + 8192 + off);
            }
            // ---- B fragments: 2 ntile-pairs x (hi, lo), one LDSM.x4 each ----
            uint32_t bhf[2][4], blf[2][4];
#pragma unroll
            for (int p = 0; p < 2; p++) {
                const int r = wn + p * 16 + rlocB;
                const uint32_t off = (uint32_t)(r * 64 + (((2 * kb + shB) ^ swm) * 16));
                LDSM4(bhf[p], base + 16384 + off);
                LDSM4(blf[p], base + 24576 + off);
            }
            // ---- 48 mmas ----
#pragma unroll
            for (int tm = 0; tm < 4; tm++)
#pragma unroll
                for (int tn = 0; tn < 4; tn++) {
                    const uint32_t* bh2 = &bhf[tn >> 1][(tn & 1) * 2];
                    const uint32_t* bl2 = &blf[tn >> 1][(tn & 1) * 2];
                    mma_bf16(acc[tm][tn], ah[tm], bh2);
                    mma_bf16(acc[tm][tn], ah[tm], bl2);
                    mma_bf16(acc[tm][tn], al[tm], bh2);
                }
        }
        if (kt + 1 < NKT) commit((kt + 1) & 1);
        __syncthreads();
    }

    // ---- epilogue: c0,c1 -> (row, col), c2,c3 -> (row+8, col) ----
#pragma unroll
    for (int tm = 0; tm < 4; tm++) {
        const size_t r0 = (size_t)rowA + wm + tm * 16 + gid;
#pragma unroll
        for (int tn = 0; tn < 4; tn++) {
            const int cn = rowB + wn + tn * 8 + tig * 2;
            *(float2*)(C + r0 * N + cn)       = make_float2(acc[tm][tn][0], acc[tm][tn][1]);
            *(float2*)(C + (r0 + 8) * N + cn) = make_float2(acc[tm][tn][2], acc[tm][tn][3]);
        }
    }
}

// ---------------- RoPE, in place. grid = B*S rows, block = nheads*32 ----------------
__global__ void rope_kernel(float* __restrict__ x, const float* __restrict__ cosp,
                            const float* __restrict__ sinp, int nheads)
{
    const int row = blockIdx.x;
    const int h = threadIdx.x >> 5, p = threadIdx.x & 31;
    const float c1 = cosp[row * 64 + p],      s1 = sinp[row * 64 + p];
    const float c2 = cosp[row * 64 + 32 + p], s2 = sinp[row * 64 + 32 + p];
    float* xr = x + ((size_t)row * nheads + h) * 64;
    const float x1 = xr[p], x2 = xr[p + 32];
    xr[p]      = x1 * c1 - x2 * s1;
    xr[p + 32] = x2 * c2 + x1 * s2;
}

__device__ void atomicMaxFloat(float* addr, float val)
{
    int* ia = (int*)addr;
    int old = *ia;
    while (__int_as_float(old) < val) {
        int assumed = old;
        old = atomicCAS(ia, assumed, __float_as_int(val));
        if (old == assumed) break;
    }
}

__global__ void init_stab_kernel(float* stab)
{
    if (threadIdx.x < B_SZ * NKV) stab[threadIdx.x] = -3.4e38f;
}

// ---------------- favor xp: xp = (x*dn) @ proj^T, also sq and (for k) head max ----
__global__ __launch_bounds__(256) void favor_xp(const float* __restrict__ x,
                                                const float* __restrict__ proj,
                                                float* __restrict__ xp,
                                                float* __restrict__ sq,
                                                float* __restrict__ stab,
                                                int nheads)
{
    __shared__ float As[32 * 68];
    __shared__ float Bs[16][256];
    __shared__ float red[256];
    const float DN = 0.35355339059327373f;
    const int s0 = blockIdx.x * 32, h = blockIdx.y, b = blockIdx.z;
    const int tid = threadIdx.x;

#pragma unroll
    for (int r = 0; r < 2; r++) {
        int l = tid + r * 256;
        int tok = l >> 4, q4 = (l & 15) << 2;
        float4 vv = *(const float4*)(x + ((size_t)(b * S_LEN + s0 + tok) * nheads + h) * 64 + q4);
        As[tok * 68 + q4 + 0] = vv.x * DN;
        As[tok * 68 + q4 + 1] = vv.y * DN;
        As[tok * 68 + q4 + 2] = vv.z * DN;
        As[tok * 68 + q4 + 3] = vv.w * DN;
    }
    __syncthreads();
    if (tid < 32) {
        float ssum = 0.f;
#pragma unroll
        for (int d = 0; d < 64; d++) { float vv = As[tid * 68 + d]; ssum += vv * vv; }
        sq[((size_t)(b * nheads + h)) * S_LEN + s0 + tid] = 0.5f * ssum;
    }

    const int tg = tid >> 5, mg = tid & 31;
    float acc[4][8];
#pragma unroll
    for (int i = 0; i < 4; i++)
#pragma unroll
        for (int j = 0; j < 8; j++) acc[i][j] = 0.f;

    for (int k0 = 0; k0 < 64; k0 += 16) {
#pragma unroll
        for (int j = 0; j < 4; j++) {
            float4 p = *(const float4*)(proj + tid * 64 + k0 + j * 4);
            Bs[j * 4 + 0][tid] = p.x; Bs[j * 4 + 1][tid] = p.y;
            Bs[j * 4 + 2][tid] = p.z; Bs[j * 4 + 3][tid] = p.w;
        }
        __syncthreads();
#pragma unroll
        for (int kk = 0; kk < 16; kk++) {
            float a[4];
#pragma unroll
            for (int i = 0; i < 4; i++) a[i] = As[(tg * 4 + i) * 68 + k0 + kk];
            float bb[8];
            *(float4*)&bb[0] = *(const float4*)&Bs[kk][mg * 8];
            *(float4*)&bb[4] = *(const float4*)&Bs[kk][mg * 8 + 4];
#pragma unroll
            for (int i = 0; i < 4; i++)
#pragma unroll
                for (int j = 0; j < 8; j++) acc[i][j] += a[i] * bb[j];
        }
        __syncthreads();
    }

    float mx = -3.4e38f;
    const size_t rowbase = (size_t)(b * nheads + h) * S_LEN + s0;
#pragma unroll
    for (int i = 0; i < 4; i++) {
        *(float4*)(xp + (rowbase + tg * 4 + i) * M_FEAT + mg * 8) =
            make_float4(acc[i][0], acc[i][1], acc[i][2], acc[i][3]);
        *(float4*)(xp + (rowbase + tg * 4 + i) * M_FEAT + mg * 8 + 4) =
            make_float4(acc[i][4], acc[i][5], acc[i][6], acc[i][7]);
        if (stab) {
#pragma unroll
            for (int j = 0; j < 8; j++) mx = fmaxf(mx, acc[i][j]);
        }
    }
    if (stab) {
        red[tid] = mx;
        __syncthreads();
        for (int st = 128; st > 0; st >>= 1) {
            if (tid < st) red[tid] = fmaxf(red[tid], red[tid + st]);
            __syncthreads();
        }
        if (tid == 0) atomicMaxFloat(&stab[b * nheads + h], red[0]);
    }
}

// ---------------- finalize phi in place ------
__global__ void favor_fin(float* __restrict__ xp, const float* __restrict__ sq,
                          const float* __restrict__ stab, int is_query, int nrows)
{
    const int warp = (blockIdx.x * blockDim.x + threadIdx.x) >> 5;
    const int lane = threadIdx.x & 31;
    if (warp >= nrows) return;
    float* row = xp + (size_t)warp * M_FEAT;
    float vals[8];
#pragma unroll
    for (int k = 0; k < 8; k++) vals[k] = row[lane + k * 32];
    float mx;
    if (is_query) {
        mx = vals[0];
#pragma unroll
        for (int k = 1; k < 8; k++) mx = fmaxf(mx, vals[k]);
#pragma unroll
        for (int o = 16; o > 0; o >>= 1) mx = fmaxf(mx, __shfl_xor_sync(0xffffffffu, mx, o));
    } else {
        mx = stab[warp / S_LEN];
    }
    const float sqv = sq[warp];
#pragma unroll
    for (int k = 0; k < 8; k++)
        row[lane + k * 32] = (expf(vals[k] - sqv - mx) + 1e-6f) * 0.0625f;
}

// ---------------- per-chunk kv (M x D) and kz (M). grid (NC, NKV, B) ---------------
__global__ __launch_bounds__(256) void kv_chunk(const float* __restrict__ phik,
                                                const float* __restrict__ v,
                                                float* __restrict__ kv,
                                                float* __restrict__ kz)
{
    __shared__ float ps[16][256];
    __shared__ float vs[16][64];
    const int c = blockIdx.x, h = blockIdx.y, b = blockIdx.z;
    const int tid = threadIdx.x;
    float acc[64];
#pragma unroll
    for (int d = 0; d < 64; d++) acc[d] = 0.f;
    float accz = 0.f;
    const size_t prow = (size_t)(b * NKV + h) * S_LEN + c * CHUNK;
    const size_t vrow = (size_t)b * S_LEN + c * CHUNK;

    for (int i0 = 0; i0 < CHUNK; i0 += 16) {
#pragma unroll
        for (int ii = 0; ii < 16; ii++)
            ps[ii][tid] = phik[(prow + i0 + ii) * M_FEAT + tid];
#pragma unroll
        for (int j = 0; j < 4; j++) {
            int l = tid + j * 256;
            int ii = l >> 6, d = l & 63;
            vs[ii][d] = v[(vrow + i0 + ii) * (NKV * D_HEAD) + h * D_HEAD + d];
        }
        __syncthreads();
#pragma unroll
        for (int ii = 0; ii < 16; ii++) {
            float a = ps[ii][tid];
            accz += a;
#pragma unroll
            for (int d4 = 0; d4 < 64; d4 += 4) {
                float4 vv = *(const float4*)&vs[ii][d4];
                acc[d4 + 0] += a * vv.x; acc[d4 + 1] += a * vv.y;
                acc[d4 + 2] += a * vv.z; acc[d4 + 3] += a * vv.w;
            }
        }
        __syncthreads();
    }
    const size_t ob = (((size_t)(b * NKV + h) * NC + c) * M_FEAT + tid) * D_HEAD;
#pragma unroll
    for (int d4 = 0; d4 < 64; d4 += 4)
        *(float4*)(kv + ob + d4) = make_float4(acc[d4], acc[d4 + 1], acc[d4 + 2], acc[d4 + 3]);
    kz[((size_t)(b * NKV + h) * NC + c) * M_FEAT + tid] = accz;
}

// ---------------- exclusive prefix over chunk axis, in place ----------------------
__global__ void cumsum_k(float* __restrict__ kv, float* __restrict__ kz)
{
    const int tid = blockIdx.x * blockDim.x + threadIdx.x;
    const int KVSZ = M_FEAT * D_HEAD;
    if (tid < B_SZ * NKV * KVSZ) {
        int bh = tid / KVSZ, md = tid % KVSZ;
        float run = 0.f;
        for (int c = 0; c < NC; c++) {
            size_t idx = ((size_t)bh * NC + c) * KVSZ + md;
            float t = kv[idx]; kv[idx] = run; run += t;
        }
    } else {
        int t2 = tid - B_SZ * NKV * KVSZ;
        if (t2 < B_SZ * NKV * M_FEAT) {
            int bh = t2 / M_FEAT, m = t2 % M_FEAT;
            float run = 0.f;
            for (int c = 0; c < NC; c++) {
                size_t idx = ((size_t)bh * NC + c) * M_FEAT + m;
                float tz = kz[idx]; kz[idx] = run; run += tz;
            }
        }
    }
}

// ---------------- chunked causal linear attention. grid (NC, NH, B) ---------------
__global__ __launch_bounds__(256) void attn_chunk(
    const float* __restrict__ phiq, const float* __restrict__ phik,
    const float* __restrict__ v, const float* __restrict__ kvpre,
    const float* __restrict__ kzpre, float* __restrict__ outp)
{
    extern __shared__ float sm[];
    float* Ss  = sm;
    float* Ast = sm + 128 * 129;
    float* Bst = Ast + 16 * 128;
    float* Vs  = Bst + 16 * 128;
    float* KZs = Vs + 16 * 64;
    float* Zs  = KZs + 16;
    float* Z2  = Zs + 128;

    const int c = blockIdx.x, h = blockIdx.y, b = blockIdx.z;
    const int kvh = h >> 2;
    const int tid = threadIdx.x;
    const int tx = tid & 15, ty = tid >> 4;

    const size_t qbase  = (size_t)(b * NH + h) * S_LEN + c * CHUNK;
    const size_t kbase  = (size_t)(b * NKV + kvh) * S_LEN + c * CHUNK;
    const size_t vbase  = (size_t)b * S_LEN + c * CHUNK;
    const size_t kvbase = ((size_t)(b * NKV + kvh) * NC + c) * (size_t)M_FEAT * D_HEAD;
    const size_t kzbase = ((size_t)(b * NKV + kvh) * NC + c) * M_FEAT;

    const int cr = tid >> 1, k8 = (tid & 1) * 8;

    {
        float acc[8][8];
#pragma unroll
        for (int i = 0; i < 8; i++)
#pragma unroll
            for (int j = 0; j < 8; j++) acc[i][j] = 0.f;

        for (int m0 = 0; m0 < M_FEAT; m0 += 16) {
#pragma unroll
            for (int j = 0; j < 8; j += 4) {
                float4 qv = *(const float4*)(phiq + (qbase + cr) * M_FEAT + m0 + k8 + j);
                Ast[(k8 + j + 0) * 128 + cr] = qv.x;
                Ast[(k8 + j + 1) * 128 + cr] = qv.y;
                Ast[(k8 + j + 2) * 128 + cr] = qv.z;
                Ast[(k8 + j + 3) * 128 + cr] = qv.w;
                float4 kk4 = *(const float4*)(phik + (kbase + cr) * M_FEAT + m0 + k8 + j);
                Bst[(k8 + j + 0) * 128 + cr] = kk4.x;
                Bst[(k8 + j + 1) * 128 + cr] = kk4.y;
                Bst[(k8 + j + 2) * 128 + cr] = kk4.z;
                Bst[(k8 + j + 3) * 128 + cr] = kk4.w;
            }
            __syncthreads();
#pragma unroll
            for (int kk = 0; kk < 16; kk++) {
                float a[8], bb[8];
                *(float4*)&a[0]  = *(const float4*)&Ast[kk * 128 + ty * 8];
                *(float4*)&a[4]  = *(const float4*)&Ast[kk * 128 + ty * 8 + 4];
                *(float4*)&bb[0] = *(const float4*)&Bst[kk * 128 + tx * 8];
                *(float4*)&bb[4] = *(const float4*)&Bst[kk * 128 + tx * 8 + 4];
#pragma unroll
                for (int i = 0; i < 8; i++)
#pragma unroll
                    for (int j = 0; j < 8; j++) acc[i][j] += a[i] * bb[j];
            }
            __syncthreads();
        }
#pragma unroll
        for (int i = 0; i < 8; i++) {
            int r = ty * 8 + i;
#pragma unroll
            for (int j = 0; j < 8; j++) {
                int t = tx * 8 + j;
                Ss[r * 129 + t] = (t <= r) ? acc[i][j] : 0.f;
            }
        }
    }
    __syncthreads();

    {
        int r = tid >> 1, hf = tid & 1;
        float zz = 0.f;
#pragma unroll
        for (int t = 0; t < 64; t++) zz += Ss[r * 129 + hf * 64 + t];
        Z2[tid] = zz;
    }

    float acc2[8][4];
#pragma unroll
    for (int i = 0; i < 8; i++)
#pragma unroll
        for (int j = 0; j < 4; j++) acc2[i][j] = 0.f;
    float zreg = 0.f;

    for (int m0 = 0; m0 < M_FEAT; m0 += 16) {
#pragma unroll
        for (int j = 0; j < 8; j += 4) {
            float4 qv = *(const float4*)(phiq + (qbase + cr) * M_FEAT + m0 + k8 + j);
            Ast[(k8 + j + 0) * 128 + cr] = qv.x;
            Ast[(k8 + j + 1) * 128 + cr] = qv.y;
            Ast[(k8 + j + 2) * 128 + cr] = qv.z;
            Ast[(k8 + j + 3) * 128 + cr] = qv.w;
        }
        {
            float4 kvv = *(const float4*)(kvpre + kvbase + (size_t)(m0 + (tid >> 4)) * 64 + (tid & 15) * 4);
            *(float4*)&Vs[(tid >> 4) * 64 + (tid & 15) * 4] = kvv;
        }
        if (tid < 16) KZs[tid] = kzpre[kzbase + m0 + tid];
        __syncthreads();
#pragma unroll
        for (int kk = 0; kk < 16; kk++) {
            float a[8];
            *(float4*)&a[0] = *(const float4*)&Ast[kk * 128 + ty * 8];
            *(float4*)&a[4] = *(const float4*)&Ast[kk * 128 + ty * 8 + 4];
            float bb[4];
            *(float4*)&bb[0] = *(const float4*)&Vs[kk * 64 + tx * 4];
#pragma unroll
            for (int i = 0; i < 8; i++)
#pragma unroll
                for (int j = 0; j < 4; j++) acc2[i][j] += a[i] * bb[j];
        }
        if (tid < 128) {
#pragma unroll
            for (int kk = 0; kk < 16; kk++)
                zreg += Ast[kk * 128 + tid] * KZs[kk];
        }
        __syncthreads();
    }
    if (tid < 128) Zs[tid] = zreg;
    __syncthreads();
    if (tid < 128) Zs[tid] += Z2[2 * tid] + Z2[2 * tid + 1];
    __syncthreads();

    for (int t0 = 0; t0 < CHUNK; t0 += 16) {
        float4 vv = *(const float4*)(v + (vbase + t0 + (tid >> 4)) * (NKV * D_HEAD) + kvh * D_HEAD + (tid & 15) * 4);
        *(float4*)&Vs[(tid >> 4) * 64 + (tid & 15) * 4] = vv;
        __syncthreads();
#pragma unroll
        for (int kk = 0; kk < 16; kk++) {
            float a[8];
#pragma unroll
            for (int i = 0; i < 8; i++) a[i] = Ss[(ty * 8 + i) * 129 + t0 + kk];
            float bb[4];
            *(float4*)&bb[0] = *(const float4*)&Vs[kk * 64 + tx * 4];
#pragma unroll
            for (int i = 0; i < 8; i++)
#pragma unroll
                for (int j = 0; j < 4; j++) acc2[i][j] += a[i] * bb[j];
        }
        __syncthreads();
    }

#pragma unroll
    for (int i = 0; i < 8; i++) {
        int r = ty * 8 + i;
        float dnm = 1.f / (Zs[r] + 1e-6f);
        float4 o = make_float4(acc2[i][0] * dnm, acc2[i][1] * dnm,
                               acc2[i][2] * dnm, acc2[i][3] * dnm);
        *(float4*)(outp + ((size_t)b * S_LEN + c * CHUNK + r) * (NH * D_HEAD) + h * D_HEAD + tx * 4) = o;
    }
}

// ----------------------------------- launch ---------------------------------------
extern "C" void kernel_launch(void* const* d_in, const int* in_sizes, int n_in,
                              void* d_out, int out_size)
{
    const float* hs   = (const float*)d_in[0];
    const float* cosp = (const float*)d_in[1];
    const float* sinp = (const float*)d_in[2];
    const float* Wq   = (const float*)d_in[3];
    const float* Wk   = (const float*)d_in[4];
    const float* Wv   = (const float*)d_in[5];
    const float* Wo   = (const float*)d_in[6];
    const float* proj = (const float*)d_in[7];
    float* out = (float*)d_out;

    float *qp, *kp, *vp, *phiqp, *phikp, *sqqp, *sqkp, *stabp, *kvp, *kzp, *attnp;
    cudaGetSymbolAddress((void**)&qp,    g_q);
    cudaGetSymbolAddress((void**)&kp,    g_k);
    cudaGetSymbolAddress((void**)&vp,    g_v);
    cudaGetSymbolAddress((void**)&phiqp, g_phiq);
    cudaGetSymbolAddress((void**)&phikp, g_phik);
    cudaGetSymbolAddress((void**)&sqqp,  g_sqq);
    cudaGetSymbolAddress((void**)&sqkp,  g_sqk);
    cudaGetSymbolAddress((void**)&stabp, g_stab);
    cudaGetSymbolAddress((void**)&kvp,   g_kv);
    cudaGetSymbolAddress((void**)&kzp,   g_kz);
    cudaGetSymbolAddress((void**)&attnp, g_attn);

    __nv_bfloat16 *hsh, *hsl, *ath, *atl, *wh, *wl;
    cudaGetSymbolAddress((void**)&hsh, g_hsh);
    cudaGetSymbolAddress((void**)&hsl, g_hsl);
    cudaGetSymbolAddress((void**)&ath, g_ath);
    cudaGetSymbolAddress((void**)&atl, g_atl);
    cudaGetSymbolAddress((void**)&wh,  g_wh);
    cudaGetSymbolAddress((void**)&wl,  g_wl);

    const int smem_attn = (128 * 129 + 2 * 16 * 128 + 16 * 64 + 16 + 128 + 256) * 4;
    cudaFuncSetAttribute(attn_chunk, cudaFuncAttributeMaxDynamicSharedMemorySize, smem_attn);
    cudaFuncSetAttribute(gemm_bf16x3, cudaFuncAttributeMaxDynamicSharedMemorySize, SMEM_GEMM);

    // ---- splits: hs + all weights ----
    split_bf16<<<(HS_ELEMS / 4 + 255) / 256, 256>>>(hs, hsh, hsl, HS_ELEMS / 4);
    split_bf16<<<(HID_ * HID_ / 4 + 255) / 256, 256>>>(Wq, wh + WQ_OFF, wl + WQ_OFF, HID_ * HID_ / 4);
    split_bf16<<<(512 * HID_ / 4 + 255) / 256, 256>>>(Wk, wh + WK_OFF, wl + WK_OFF, 512 * HID_ / 4);
    split_bf16<<<(512 * HID_ / 4 + 255) / 256, 256>>>(Wv, wh + WV_OFF, wl + WV_OFF, 512 * HID_ / 4);
    split_bf16<<<(HID_ * HID_ / 4 + 255) / 256, 256>>>(Wo, wh + WO_OFF, wl + WO_OFF, HID_ * HID_ / 4);

    // ---- QKV projections (bf16 split, tensor cores, ldmatrix path) ----
    gemm_bf16x3<<<dim3(16, 32), 256, SMEM_GEMM>>>(hsh, hsl, wh + WQ_OFF, wl + WQ_OFF, qp, 2048);
    gemm_bf16x3<<<dim3(4, 32), 256, SMEM_GEMM>>>(hsh, hsl, wh + WK_OFF, wl + WK_OFF, kp, 512);
    gemm_bf16x3<<<dim3(4, 32), 256, SMEM_GEMM>>>(hsh, hsl, wh + WV_OFF, wl + WV_OFF, vp, 512);

    // ---- RoPE ----
    rope_kernel<<<B_SZ * S_LEN, NH * 32>>>(qp, cosp, sinp, NH);
    rope_kernel<<<B_SZ * S_LEN, NKV * 32>>>(kp, cosp, sinp, NKV);

    // ---- favor features ----
    init_stab_kernel<<<1, 32>>>(stabp);
    favor_xp<<<dim3(S_LEN / 32, NH, B_SZ), 256>>>(qp, proj, phiqp, sqqp, nullptr, NH);
    favor_xp<<<dim3(S_LEN / 32, NKV, B_SZ), 256>>>(kp, proj, phikp, sqkp, stabp, NKV);
    favor_fin<<<(B_SZ * NH * S_LEN) / 8, 256>>>(phiqp, sqqp, nullptr, 1, B_SZ * NH * S_LEN);
    favor_fin<<<(B_SZ * NKV * S_LEN) / 8, 256>>>(phikp, sqkp, stabp, 0, B_SZ * NKV * S_LEN);

    // ---- chunked linear attention ----
    kv_chunk<<<dim3(NC, NKV, B_SZ), 256>>>(phikp, vp, kvp, kzp);
    cumsum_k<<<(B_SZ * NKV * (M_FEAT * D_HEAD + M_FEAT) + 255) / 256, 256>>>(kvp, kzp);
    attn_chunk<<<dim3(NC, NH, B_SZ), 256, smem_attn>>>(phiqp, phikp, vp, kvp, kzp, attnp);

    // ---- output projection ----
    split_bf16<<<(HS_ELEMS / 4 + 255) / 256, 256>>>(attnp, ath, atl, HS_ELEMS / 4);
    gemm_bf16x3<<<dim3(16, 32), 256, SMEM_GEMM>>>(ath, atl, wh + WO_OFF, wl + WO_OFF, out, 2048);
}

// round 7
// speedup vs baseline: 1.4302x; 1.0694x over previous
#include <cuda_runtime.h>
#include <cuda_bf16.h>
#include <math.h>
#include <stdint.h>

#define B_SZ   2
#define S_LEN  2048
#define HID_   2048
#define NH     32
#define NKV    8
#define D_HEAD 64
#define M_FEAT 256
#define NC     16
#define CHUNK  128
#define QKVW   3072          // combined q|k|v column width

// ---------------- scratch (device globals; no allocations allowed) ----------------
__device__ float g_qkv [(size_t)B_SZ * S_LEN * QKVW];          // q: cols 0..2047, k: 2048..2559, v: 2560..3071
__device__ float g_phiq[(size_t)B_SZ * NH  * S_LEN * M_FEAT];
__device__ float g_phik[(size_t)B_SZ * NKV * S_LEN * M_FEAT];
__device__ float g_sqk [B_SZ * NKV * S_LEN];
__device__ float g_stab[B_SZ * NKV];
__device__ float g_kv  [B_SZ * NKV * NC * M_FEAT * D_HEAD];
__device__ float g_kz  [B_SZ * NKV * NC * M_FEAT];
__device__ float g_attn[B_SZ * S_LEN * NH * D_HEAD];

// bf16 hi/lo split buffers (16B-aligned for uint4 access)
#define HS_ELEMS  (B_SZ * S_LEN * HID_)
#define W_ELEMS   (QKVW * HID_ + HID_ * HID_)
__device__ __align__(16) __nv_bfloat16 g_hsh[HS_ELEMS];
__device__ __align__(16) __nv_bfloat16 g_hsl[HS_ELEMS];
__device__ __align__(16) __nv_bfloat16 g_ath[HS_ELEMS];
__device__ __align__(16) __nv_bfloat16 g_atl[HS_ELEMS];
__device__ __align__(16) __nv_bfloat16 g_wh [W_ELEMS];
__device__ __align__(16) __nv_bfloat16 g_wl [W_ELEMS];

#define WQ_OFF 0
#define WK_OFF (HID_ * HID_)
#define WV_OFF (WK_OFF + 512 * HID_)
#define WO_OFF (WV_OFF + 512 * HID_)

// =================== fp32 -> bf16 hi/lo split (elementwise, x4 vec) ================
__global__ void split_bf16(const float* __restrict__ x, __nv_bfloat16* __restrict__ h,
                           __nv_bfloat16* __restrict__ l, int n4)
{
    int i = blockIdx.x * blockDim.x + threadIdx.x;
    if (i >= n4) return;
    float4 v = ((const float4*)x)[i];
    __nv_bfloat16 h0 = __float2bfloat16(v.x), h1 = __float2bfloat16(v.y);
    __nv_bfloat16 h2 = __float2bfloat16(v.z), h3 = __float2bfloat16(v.w);
    __nv_bfloat162* hp = (__nv_bfloat162*)h;
    hp[2 * i]     = __nv_bfloat162(h0, h1);
    hp[2 * i + 1] = __nv_bfloat162(h2, h3);
    __nv_bfloat162* lp = (__nv_bfloat162*)l;
    lp[2 * i]     = __nv_bfloat162(__float2bfloat16(v.x - __bfloat162float(h0)),
                                   __float2bfloat16(v.y - __bfloat162float(h1)));
    lp[2 * i + 1] = __nv_bfloat162(__float2bfloat16(v.z - __bfloat162float(h2)),
                                   __float2bfloat16(v.w - __bfloat162float(h3)));
}

// ===================== shared helpers for tensor-core kernels ======================
__device__ __forceinline__ uint32_t smem_u32g(const void* p)
{
    uint32_t a;
    asm("{ .reg .u64 t; cvta.to.shared.u64 t, %1; cvt.u32.u64 %0, t; }" : "=r"(a) : "l"(p));
    return a;
}

#define LDSM4(r, a) \
    asm volatile("ldmatrix.sync.aligned.m8n8.x4.shared.b16 {%0,%1,%2,%3}, [%4];" \
                 : "=r"((r)[0]), "=r"((r)[1]), "=r"((r)[2]), "=r"((r)[3]) : "r"(a))

__device__ __forceinline__ void mma_bf16(float c[4], const uint32_t a[4], const uint32_t b[2])
{
    asm volatile("mma.sync.aligned.m16n8k16.row.col.f32.bf16.bf16.f32 "
                 "{%0,%1,%2,%3}, {%4,%5,%6,%7}, {%8,%9}, {%0,%1,%2,%3};"
                 : "+f"(c[0]), "+f"(c[1]), "+f"(c[2]), "+f"(c[3])
                 : "r"(a[0]), "r"(a[1]), "r"(a[2]), "r"(a[3]), "r"(b[0]), "r"(b[1]));
}

// ======== bf16 3-pass split GEMM: ldmatrix + swizzled smem, m16n8k16 ===============
#define GK 2048
#define BK 32
#define NKT (GK / BK)
#define GBUF 32768
#define SMEM_GEMM (2 * GBUF)

__global__ __launch_bounds__(256, 1) void gemm_bf16x3(const __nv_bfloat16* __restrict__ Ah,
                                                      const __nv_bfloat16* __restrict__ Al,
                                                      const __nv_bfloat16* __restrict__ Bh,
                                                      const __nv_bfloat16* __restrict__ Bl,
                                                      float* __restrict__ C, int N)
{
    extern __shared__ char smc[];
    const uint32_t sb = smem_u32g(smc);
    const int tid  = threadIdx.x;
    const int warp = tid >> 5, lane = tid & 31;
    const int gid  = lane >> 2, tig = lane & 3;
    const int wm   = (warp & 1) * 64;
    const int wn   = (warp >> 1) * 32;
    const int rowA = blockIdx.y * 128;
    const int rowB = blockIdx.x * 128;

    const int st_row  = tid >> 2;
    const int st_slot = tid & 3;
    const uint32_t st_off0 = (uint32_t)(st_row * 64 + ((st_slot ^ ((st_row >> 1) & 3)) * 16));
    const int st_row1 = st_row + 64;
    const uint32_t st_off1 = (uint32_t)(st_row1 * 64 + ((st_slot ^ ((st_row1 >> 1) & 3)) * 16));

    const int swm   = ((lane & 7) >> 1) & 3;
    const int rlocA = (lane & 7) + (((lane >> 3) & 1) << 3);
    const int shA   = lane >> 4;
    const int rlocB = (lane & 7) + ((lane >> 4) << 3);
    const int shB   = (lane >> 3) & 1;

    float acc[4][4][4];
#pragma unroll
    for (int i = 0; i < 4; i++)
#pragma unroll
        for (int j = 0; j < 4; j++)
#pragma unroll
            for (int r = 0; r < 4; r++) acc[i][j][r] = 0.f;

    uint4 pAh[2], pAl[2], pBh[2], pBl[2];

    auto prefetch = [&](int kt) {
        const int kb = kt * BK;
        pAh[0] = *(const uint4*)(Ah + (size_t)(rowA + st_row)  * GK + kb + st_slot * 8);
        pAh[1] = *(const uint4*)(Ah + (size_t)(rowA + st_row1) * GK + kb + st_slot * 8);
        pAl[0] = *(const uint4*)(Al + (size_t)(rowA + st_row)  * GK + kb + st_slot * 8);
        pAl[1] = *(const uint4*)(Al + (size_t)(rowA + st_row1) * GK + kb + st_slot * 8);
        pBh[0] = *(const uint4*)(Bh + (size_t)(rowB + st_row)  * GK + kb + st_slot * 8);
        pBh[1] = *(const uint4*)(Bh + (size_t)(rowB + st_row1) * GK + kb + st_slot * 8);
        pBl[0] = *(const uint4*)(Bl + (size_t)(rowB + st_row)  * GK + kb + st_slot * 8);
        pBl[1] = *(const uint4*)(Bl + (size_t)(rowB + st_row1) * GK + kb + st_slot * 8);
    };
    auto commit = [&](int b) {
        char* buf = smc + b * GBUF;
        *(uint4*)(buf + st_off0)         = pAh[0];
        *(uint4*)(buf + st_off1)         = pAh[1];
        *(uint4*)(buf + 8192  + st_off0) = pAl[0];
        *(uint4*)(buf + 8192  + st_off1) = pAl[1];
        *(uint4*)(buf + 16384 + st_off0) = pBh[0];
        *(uint4*)(buf + 16384 + st_off1) = pBh[1];
        *(uint4*)(buf + 24576 + st_off0) = pBl[0];
        *(uint4*)(buf + 24576 + st_off1) = pBl[1];
    };

    prefetch(0);
    commit(0);
    __syncthreads();

    for (int kt = 0; kt < NKT; kt++) {
        const uint32_t base = sb + (kt & 1) * GBUF;
        if (kt + 1 < NKT) prefetch(kt + 1);

#pragma unroll
        for (int kb = 0; kb < 2; kb++) {
            uint32_t ah[4][4], al[4][4];
#pragma unroll
            for (int tm = 0; tm < 4; tm++) {
                const int r = wm + tm * 16 + rlocA;
                const uint32_t off = (uint32_t)(r * 64 + (((2 * kb + shA) ^ swm) * 16));
                LDSM4(ah[tm], base + off);
                LDSM4(al[tm], base + 8192 + off);
            }
            uint32_t bhf[2][4], blf[2][4];
#pragma unroll
            for (int p = 0; p < 2; p++) {
                const int r = wn + p * 16 + rlocB;
                const uint32_t off = (uint32_t)(r * 64 + (((2 * kb + shB) ^ swm) * 16));
                LDSM4(bhf[p], base + 16384 + off);
                LDSM4(blf[p], base + 24576 + off);
            }
#pragma unroll
            for (int tm = 0; tm < 4; tm++)
#pragma unroll
                for (int tn = 0; tn < 4; tn++) {
                    const uint32_t* bh2 = &bhf[tn >> 1][(tn & 1) * 2];
                    const uint32_t* bl2 = &blf[tn >> 1][(tn & 1) * 2];
                    mma_bf16(acc[tm][tn], ah[tm], bh2);
                    mma_bf16(acc[tm][tn], ah[tm], bl2);
                    mma_bf16(acc[tm][tn], al[tm], bh2);
                }
        }
        if (kt + 1 < NKT) commit((kt + 1) & 1);
        __syncthreads();
    }

#pragma unroll
    for (int tm = 0; tm < 4; tm++) {
        const size_t r0 = (size_t)rowA + wm + tm * 16 + gid;
#pragma unroll
        for (int tn = 0; tn < 4; tn++) {
            const int cn = rowB + wn + tn * 8 + tig * 2;
            *(float2*)(C + r0 * N + cn)       = make_float2(acc[tm][tn][0], acc[tm][tn][1]);
            *(float2*)(C + (r0 + 8) * N + cn) = make_float2(acc[tm][tn][2], acc[tm][tn][3]);
        }
    }
}

// ---------------- RoPE, in place on combined buffer --------------------------------
__global__ void rope_kernel(float* __restrict__ x, const float* __restrict__ cosp,
                            const float* __restrict__ sinp, int stride, int coloff)
{
    const int row = blockIdx.x;
    const int h = threadIdx.x >> 5, p = threadIdx.x & 31;
    const float c1 = cosp[row * 64 + p],      s1 = sinp[row * 64 + p];
    const float c2 = cosp[row * 64 + 32 + p], s2 = sinp[row * 64 + 32 + p];
    float* xr = x + (size_t)row * stride + coloff + h * 64;
    const float x1 = xr[p], x2 = xr[p + 32];
    xr[p]      = x1 * c1 - x2 * s1;
    xr[p + 32] = x2 * c2 + x1 * s2;
}

__device__ void atomicMaxFloat(float* addr, float val)
{
    int* ia = (int*)addr;
    int old = *ia;
    while (__int_as_float(old) < val) {
        int assumed = old;
        old = atomicCAS(ia, assumed, __float_as_int(val));
        if (old == assumed) break;
    }
}

__global__ void init_stab_kernel(float* stab)
{
    if (threadIdx.x < B_SZ * NKV) stab[threadIdx.x] = -3.4e38f;
}

// ---------------- favor xp (+fused q exp when stab==null) --------------------------
__global__ __launch_bounds__(256) void favor_xp(const float* __restrict__ x,
                                                const float* __restrict__ proj,
                                                float* __restrict__ xp,
                                                float* __restrict__ sq,
                                                float* __restrict__ stab,
                                                int nheads, int xstride, int xcoloff)
{
    __shared__ float As[32 * 68];
    __shared__ float Bs[16][256];
    __shared__ float red[256];
    __shared__ float sqsh[32];
    const float DN = 0.35355339059327373f;
    const int s0 = blockIdx.x * 32, h = blockIdx.y, b = blockIdx.z;
    const int tid = threadIdx.x;

#pragma unroll
    for (int r = 0; r < 2; r++) {
        int l = tid + r * 256;
        int tok = l >> 4, q4 = (l & 15) << 2;
        float4 vv = *(const float4*)(x + (size_t)(b * S_LEN + s0 + tok) * xstride + xcoloff + h * 64 + q4);
        As[tok * 68 + q4 + 0] = vv.x * DN;
        As[tok * 68 + q4 + 1] = vv.y * DN;
        As[tok * 68 + q4 + 2] = vv.z * DN;
        As[tok * 68 + q4 + 3] = vv.w * DN;
    }
    __syncthreads();
    if (tid < 32) {
        float ssum = 0.f;
#pragma unroll
        for (int d = 0; d < 64; d++) { float vv = As[tid * 68 + d]; ssum += vv * vv; }
        sqsh[tid] = 0.5f * ssum;
        if (sq) sq[((size_t)(b * nheads + h)) * S_LEN + s0 + tid] = 0.5f * ssum;
    }

    const int tg = tid >> 5, mg = tid & 31;
    float acc[4][8];
#pragma unroll
    for (int i = 0; i < 4; i++)
#pragma unroll
        for (int j = 0; j < 8; j++) acc[i][j] = 0.f;

    for (int k0 = 0; k0 < 64; k0 += 16) {
#pragma unroll
        for (int j = 0; j < 4; j++) {
            float4 p = *(const float4*)(proj + tid * 64 + k0 + j * 4);
            Bs[j * 4 + 0][tid] = p.x; Bs[j * 4 + 1][tid] = p.y;
            Bs[j * 4 + 2][tid] = p.z; Bs[j * 4 + 3][tid] = p.w;
        }
        __syncthreads();
#pragma unroll
        for (int kk = 0; kk < 16; kk++) {
            float a[4];
#pragma unroll
            for (int i = 0; i < 4; i++) a[i] = As[(tg * 4 + i) * 68 + k0 + kk];
            float bb[8];
            *(float4*)&bb[0] = *(const float4*)&Bs[kk][mg * 8];
            *(float4*)&bb[4] = *(const float4*)&Bs[kk][mg * 8 + 4];
#pragma unroll
            for (int i = 0; i < 4; i++)
#pragma unroll
                for (int j = 0; j < 8; j++) acc[i][j] += a[i] * bb[j];
        }
        __syncthreads();
    }

    if (stab == nullptr) {
        // fused q path: per-row max (warp lanes == m-groups) then exp
#pragma unroll
        for (int i = 0; i < 4; i++) {
            float m = acc[i][0];
#pragma unroll
            for (int j = 1; j < 8; j++) m = fmaxf(m, acc[i][j]);
#pragma unroll
            for (int o = 16; o > 0; o >>= 1) m = fmaxf(m, __shfl_xor_sync(0xffffffffu, m, o));
            const float sv = sqsh[tg * 4 + i];
#pragma unroll
            for (int j = 0; j < 8; j++)
                acc[i][j] = (expf(acc[i][j] - sv - m) + 1e-6f) * 0.0625f;
        }
    }

    float mx = -3.4e38f;
    const size_t rowbase = (size_t)(b * nheads + h) * S_LEN + s0;
#pragma unroll
    for (int i = 0; i < 4; i++) {
        *(float4*)(xp + (rowbase + tg * 4 + i) * M_FEAT + mg * 8) =
            make_float4(acc[i][0], acc[i][1], acc[i][2], acc[i][3]);
        *(float4*)(xp + (rowbase + tg * 4 + i) * M_FEAT + mg * 8 + 4) =
            make_float4(acc[i][4], acc[i][5], acc[i][6], acc[i][7]);
        if (stab) {
#pragma unroll
            for (int j = 0; j < 8; j++) mx = fmaxf(mx, acc[i][j]);
        }
    }
    if (stab) {
        red[tid] = mx;
        __syncthreads();
        for (int st = 128; st > 0; st >>= 1) {
            if (tid < st) red[tid] = fmaxf(red[tid], red[tid + st]);
            __syncthreads();
        }
        if (tid == 0) atomicMaxFloat(&stab[b * nheads + h], red[0]);
    }
}

// ---------------- finalize phi in place (k only) -----------------------------------
__global__ void favor_fin(float* __restrict__ xp, const float* __restrict__ sq,
                          const float* __restrict__ stab, int nrows)
{
    const int warp = (blockIdx.x * blockDim.x + threadIdx.x) >> 5;
    const int lane = threadIdx.x & 31;
    if (warp >= nrows) return;
    float* row = xp + (size_t)warp * M_FEAT;
    const float mx  = stab[warp / S_LEN];
    const float sqv = sq[warp];
#pragma unroll
    for (int k = 0; k < 8; k++) {
        float v = row[lane + k * 32];
        row[lane + k * 32] = (expf(v - sqv - mx) + 1e-6f) * 0.0625f;
    }
}

// ---------------- per-chunk kv (M x D) and kz (M). grid (NC, NKV, B) ---------------
__global__ __launch_bounds__(256) void kv_chunk(const float* __restrict__ phik,
                                                const float* __restrict__ qkv,
                                                float* __restrict__ kv,
                                                float* __restrict__ kz)
{
    __shared__ float ps[16][256];
    __shared__ float vs[16][64];
    const int c = blockIdx.x, h = blockIdx.y, b = blockIdx.z;
    const int tid = threadIdx.x;
    float acc[64];
#pragma unroll
    for (int d = 0; d < 64; d++) acc[d] = 0.f;
    float accz = 0.f;
    const size_t prow = (size_t)(b * NKV + h) * S_LEN + c * CHUNK;
    const size_t vrow = (size_t)b * S_LEN + c * CHUNK;

    for (int i0 = 0; i0 < CHUNK; i0 += 16) {
#pragma unroll
        for (int ii = 0; ii < 16; ii++)
            ps[ii][tid] = phik[(prow + i0 + ii) * M_FEAT + tid];
#pragma unroll
        for (int j = 0; j < 4; j++) {
            int l = tid + j * 256;
            int ii = l >> 6, d = l & 63;
            vs[ii][d] = qkv[(vrow + i0 + ii) * QKVW + 2560 + h * 64 + d];
        }
        __syncthreads();
#pragma unroll
        for (int ii = 0; ii < 16; ii++) {
            float a = ps[ii][tid];
            accz += a;
#pragma unroll
            for (int d4 = 0; d4 < 64; d4 += 4) {
                float4 vv = *(const float4*)&vs[ii][d4];
                acc[d4 + 0] += a * vv.x; acc[d4 + 1] += a * vv.y;
                acc[d4 + 2] += a * vv.z; acc[d4 + 3] += a * vv.w;
            }
        }
        __syncthreads();
    }
    const size_t ob = (((size_t)(b * NKV + h) * NC + c) * M_FEAT + tid) * D_HEAD;
#pragma unroll
    for (int d4 = 0; d4 < 64; d4 += 4)
        *(float4*)(kv + ob + d4) = make_float4(acc[d4], acc[d4 + 1], acc[d4 + 2], acc[d4 + 3]);
    kz[((size_t)(b * NKV + h) * NC + c) * M_FEAT + tid] = accz;
}

// ---------------- exclusive prefix over chunk axis, in place ----------------------
__global__ void cumsum_k(float* __restrict__ kv, float* __restrict__ kz)
{
    const int tid = blockIdx.x * blockDim.x + threadIdx.x;
    const int KVSZ = M_FEAT * D_HEAD;
    if (tid < B_SZ * NKV * KVSZ) {
        int bh = tid / KVSZ, md = tid % KVSZ;
        float run = 0.f;
        for (int c = 0; c < NC; c++) {
            size_t idx = ((size_t)bh * NC + c) * KVSZ + md;
            float t = kv[idx]; kv[idx] = run; run += t;
        }
    } else {
        int t2 = tid - B_SZ * NKV * KVSZ;
        if (t2 < B_SZ * NKV * M_FEAT) {
            int bh = t2 / M_FEAT, m = t2 % M_FEAT;
            float run = 0.f;
            for (int c = 0; c < NC; c++) {
                size_t idx = ((size_t)bh * NC + c) * M_FEAT + m;
                float tz = kz[idx]; kz[idx] = run; run += tz;
            }
        }
    }
}

// ============ tensor-core chunked causal linear attention. grid (NC, NH, B) ========
// Phase 1: S = mask(phiq_c @ phik_c^T)      (128x128, K=256, bf16 hi/lo 3-pass)
// Phase 2: [out | z] = phiq_c @ [kv|kz]  +  S @ [v|1]   (128x80, K=384 composite)
#define SPITCH 132
#define SMEM_ATTN (128 * SPITCH * 4 + 4 * 8192 + 512)

__global__ __launch_bounds__(256, 1) void attn_tc(
    const float* __restrict__ phiq, const float* __restrict__ phik,
    const float* __restrict__ qkv, const float* __restrict__ kvpre,
    const float* __restrict__ kzpre, float* __restrict__ outp)
{
    extern __shared__ float sm[];
    float* Ss = sm;
    char* Ah = (char*)(sm + 128 * SPITCH);
    char* Al = Ah + 8192;
    char* Bh = Al + 8192;
    char* Bl = Bh + 8192;
    float* Zs = (float*)(Bl + 8192);

    const uint32_t sbAh = smem_u32g(Ah), sbAl = smem_u32g(Al);
    const uint32_t sbBh = smem_u32g(Bh), sbBl = smem_u32g(Bl);

    const int c = blockIdx.x, h = blockIdx.y, b = blockIdx.z;
    const int kvh = h >> 2;
    const int tid = threadIdx.x;
    const int warp = tid >> 5, lane = tid & 31;
    const int gid = lane >> 2, tig = lane & 3;

    const size_t qbase  = (size_t)(b * NH + h) * S_LEN + c * CHUNK;
    const size_t kbase  = (size_t)(b * NKV + kvh) * S_LEN + c * CHUNK;
    const size_t vrow0  = (size_t)b * S_LEN + c * CHUNK;
    const size_t kvbase = ((size_t)(b * NKV + kvh) * NC + c) * (size_t)(M_FEAT * D_HEAD);
    const size_t kzbase = ((size_t)(b * NKV + kvh) * NC + c) * M_FEAT;

    const int strow = tid & 127;
    const int s0 = tid >> 7;

    const int swm   = ((lane & 7) >> 1) & 3;
    const int rlocA = (lane & 7) + (((lane >> 3) & 1) << 3);
    const int shA   = lane >> 4;
    const int rlocB = (lane & 7) + ((lane >> 4) << 3);
    const int shB   = (lane >> 3) & 1;

    auto cvt_store = [&](char* hb, char* lb, int row, int slot, const float* f) {
        uint32_t hw[4], lw[4];
#pragma unroll
        for (int e = 0; e < 4; e++) {
            __nv_bfloat16 h0 = __float2bfloat16(f[2 * e]);
            __nv_bfloat16 h1 = __float2bfloat16(f[2 * e + 1]);
            __nv_bfloat162 hp(h0, h1);
            hw[e] = *(uint32_t*)&hp;
            __nv_bfloat162 lp(__float2bfloat16(f[2 * e]     - __bfloat162float(h0)),
                              __float2bfloat16(f[2 * e + 1] - __bfloat162float(h1)));
            lw[e] = *(uint32_t*)&lp;
        }
        uint32_t off = (uint32_t)(row * 64 + ((slot ^ ((row >> 1) & 3)) * 16));
        *(uint4*)(hb + off) = make_uint4(hw[0], hw[1], hw[2], hw[3]);
        *(uint4*)(lb + off) = make_uint4(lw[0], lw[1], lw[2], lw[3]);
    };

    // ======================= Phase 1: scores =======================
    {
        const int wm = (warp & 1) * 64, wn = (warp >> 1) * 32;
        float acc[4][4][4];
#pragma unroll
        for (int i = 0; i < 4; i++)
#pragma unroll
            for (int j = 0; j < 4; j++)
#pragma unroll
                for (int r = 0; r < 4; r++) acc[i][j][r] = 0.f;

        for (int m0 = 0; m0 < M_FEAT; m0 += 32) {
#pragma unroll
            for (int si = 0; si < 2; si++) {
                const int s = s0 + si * 2;
                float f[8];
                const float* pa = phiq + (qbase + strow) * M_FEAT + m0 + s * 8;
                *(float4*)&f[0] = *(const float4*)pa;
                *(float4*)&f[4] = *(const float4*)(pa + 4);
                cvt_store(Ah, Al, strow, s, f);
                const float* pb = phik + (kbase + strow) * M_FEAT + m0 + s * 8;
                *(float4*)&f[0] = *(const float4*)pb;
                *(float4*)&f[4] = *(const float4*)(pb + 4);
                cvt_store(Bh, Bl, strow, s, f);
            }
            __syncthreads();
#pragma unroll
            for (int kb = 0; kb < 2; kb++) {
                uint32_t ah[4][4], al[4][4];
#pragma unroll
                for (int tm = 0; tm < 4; tm++) {
                    const int r = wm + tm * 16 + rlocA;
                    const uint32_t off = (uint32_t)(r * 64 + (((2 * kb + shA) ^ swm) * 16));
                    LDSM4(ah[tm], sbAh + off);
                    LDSM4(al[tm], sbAl + off);
                }
                uint32_t bhf[2][4], blf[2][4];
#pragma unroll
                for (int p = 0; p < 2; p++) {
                    const int r = wn + p * 16 + rlocB;
                    const uint32_t off = (uint32_t)(r * 64 + (((2 * kb + shB) ^ swm) * 16));
                    LDSM4(bhf[p], sbBh + off);
                    LDSM4(blf[p], sbBl + off);
                }
#pragma unroll
                for (int tm = 0; tm < 4; tm++)
#pragma unroll
                    for (int tn = 0; tn < 4; tn++) {
                        const uint32_t* bh2 = &bhf[tn >> 1][(tn & 1) * 2];
                        const uint32_t* bl2 = &blf[tn >> 1][(tn & 1) * 2];
                        mma_bf16(acc[tm][tn], ah[tm], bh2);
                        mma_bf16(acc[tm][tn], ah[tm], bl2);
                        mma_bf16(acc[tm][tn], al[tm], bh2);
                    }
            }
            __syncthreads();
        }
        // mask + write S (fp32, pitch 132)
#pragma unroll
        for (int tm = 0; tm < 4; tm++) {
            const int r0 = wm + tm * 16 + gid;
            const int r1 = r0 + 8;
#pragma unroll
            for (int tn = 0; tn < 4; tn++) {
                const int col = wn + tn * 8 + tig * 2;
                Ss[r0 * SPITCH + col]     = (col     <= r0) ? acc[tm][tn][0] : 0.f;
                Ss[r0 * SPITCH + col + 1] = (col + 1 <= r0) ? acc[tm][tn][1] : 0.f;
                Ss[r1 * SPITCH + col]     = (col     <= r1) ? acc[tm][tn][2] : 0.f;
                Ss[r1 * SPITCH + col + 1] = (col + 1 <= r1) ? acc[tm][tn][3] : 0.f;
            }
        }
    }
    __syncthreads();

    // ======================= Phase 2: inter+intra (+z col 64) =======================
    const int wm2 = (warp & 3) * 32, wn2 = (warp >> 2) * 40;
    float acc2[2][5][4];
#pragma unroll
    for (int i = 0; i < 2; i++)
#pragma unroll
        for (int j = 0; j < 5; j++)
#pragma unroll
            for (int r = 0; r < 4; r++) acc2[i][j][r] = 0.f;

    for (int cc = 0; cc < 12; cc++) {
#pragma unroll
        for (int si = 0; si < 2; si++) {
            const int s = s0 + si * 2;
            float f[8];
            if (cc < 8) {
                const float* pa = phiq + (qbase + strow) * M_FEAT + cc * 32 + s * 8;
                *(float4*)&f[0] = *(const float4*)pa;
                *(float4*)&f[4] = *(const float4*)(pa + 4);
            } else {
                const float* pa = Ss + strow * SPITCH + (cc - 8) * 32 + s * 8;
                *(float4*)&f[0] = *(const float4*)pa;
                *(float4*)&f[4] = *(const float4*)(pa + 4);
            }
            cvt_store(Ah, Al, strow, s, f);

            if (strow < 96) {
                float g[8];
                if (strow < 64) {
                    if (cc < 8) {
#pragma unroll
                        for (int e = 0; e < 8; e++)
                            g[e] = kvpre[kvbase + (size_t)(cc * 32 + s * 8 + e) * 64 + strow];
                    } else {
#pragma unroll
                        for (int e = 0; e < 8; e++)
                            g[e] = qkv[(vrow0 + (cc - 8) * 32 + s * 8 + e) * QKVW + 2560 + kvh * 64 + strow];
                    }
                } else if (strow == 64) {
                    if (cc < 8) {
#pragma unroll
                        for (int e = 0; e < 8; e++)
                            g[e] = kzpre[kzbase + cc * 32 + s * 8 + e];
                    } else {
#pragma unroll
                        for (int e = 0; e < 8; e++) g[e] = 1.f;
                    }
                } else {
#pragma unroll
                    for (int e = 0; e < 8; e++) g[e] = 0.f;
                }
                cvt_store(Bh, Bl, strow, s, g);
            }
        }
        __syncthreads();
#pragma unroll
        for (int kb = 0; kb < 2; kb++) {
            uint32_t ah2[2][4], al2[2][4], bh2[3][4], bl2[3][4];
#pragma unroll
            for (int tm = 0; tm < 2; tm++) {
                const int r = wm2 + tm * 16 + rlocA;
                const uint32_t off = (uint32_t)(r * 64 + (((2 * kb + shA) ^ swm) * 16));
                LDSM4(ah2[tm], sbAh + off);
                LDSM4(al2[tm], sbAl + off);
            }
#pragma unroll
            for (int p = 0; p < 3; p++) {
                const int r = wn2 + p * 16 + rlocB;
                const uint32_t off = (uint32_t)(r * 64 + (((2 * kb + shB) ^ swm) * 16));
                LDSM4(bh2[p], sbBh + off);
                LDSM4(bl2[p], sbBl + off);
            }
#pragma unroll
            for (int tm = 0; tm < 2; tm++)
#pragma unroll
                for (int tn = 0; tn < 5; tn++) {
                    const uint32_t* bh_ = &bh2[tn >> 1][(tn & 1) * 2];
                    const uint32_t* bl_ = &bl2[tn >> 1][(tn & 1) * 2];
                    mma_bf16(acc2[tm][tn], ah2[tm], bh_);
                    mma_bf16(acc2[tm][tn], ah2[tm], bl_);
                    mma_bf16(acc2[tm][tn], al2[tm], bh_);
                }
        }
        __syncthreads();
    }

    // z column (col 64 = wn2 40 + tn3*8 = 64, tig 0) -> smem
    if ((warp >> 2) == 1 && tig == 0) {
#pragma unroll
        for (int tm = 0; tm < 2; tm++) {
            const int r = wm2 + tm * 16 + gid;
            Zs[r]     = acc2[tm][3][0];
            Zs[r + 8] = acc2[tm][3][2];
        }
    }
    __syncthreads();

    // epilogue: divide + write (cols < 64 only)
#pragma unroll
    for (int tm = 0; tm < 2; tm++) {
        const int r = wm2 + tm * 16 + gid;
        const float d0 = 1.f / (Zs[r] + 1e-6f);
        const float d1 = 1.f / (Zs[r + 8] + 1e-6f);
#pragma unroll
        for (int tn = 0; tn < 5; tn++) {
            const int col = wn2 + tn * 8 + tig * 2;
            if (col < 64) {
                const size_t ro = ((size_t)b * S_LEN + c * CHUNK + r) * (NH * D_HEAD) + h * 64 + col;
                *(float2*)(outp + ro) = make_float2(acc2[tm][tn][0] * d0, acc2[tm][tn][1] * d0);
                *(float2*)(outp + ro + 8 * (NH * D_HEAD)) =
                    make_float2(acc2[tm][tn][2] * d1, acc2[tm][tn][3] * d1);
            }
        }
    }
}

// ----------------------------------- launch ---------------------------------------
extern "C" void kernel_launch(void* const* d_in, const int* in_sizes, int n_in,
                              void* d_out, int out_size)
{
    const float* hs   = (const float*)d_in[0];
    const float* cosp = (const float*)d_in[1];
    const float* sinp = (const float*)d_in[2];
    const float* Wq   = (const float*)d_in[3];
    const float* Wk   = (const float*)d_in[4];
    const float* Wv   = (const float*)d_in[5];
    const float* Wo   = (const float*)d_in[6];
    const float* proj = (const float*)d_in[7];
    float* out = (float*)d_out;

    float *qkvp, *phiqp, *phikp, *sqkp, *stabp, *kvp, *kzp, *attnp;
    cudaGetSymbolAddress((void**)&qkvp,  g_qkv);
    cudaGetSymbolAddress((void**)&phiqp, g_phiq);
    cudaGetSymbolAddress((void**)&phikp, g_phik);
    cudaGetSymbolAddress((void**)&sqkp,  g_sqk);
    cudaGetSymbolAddress((void**)&stabp, g_stab);
    cudaGetSymbolAddress((void**)&kvp,   g_kv);
    cudaGetSymbolAddress((void**)&kzp,   g_kz);
    cudaGetSymbolAddress((void**)&attnp, g_attn);

    __nv_bfloat16 *hsh, *hsl, *ath, *atl, *wh, *wl;
    cudaGetSymbolAddress((void**)&hsh, g_hsh);
    cudaGetSymbolAddress((void**)&hsl, g_hsl);
    cudaGetSymbolAddress((void**)&ath, g_ath);
    cudaGetSymbolAddress((void**)&atl, g_atl);
    cudaGetSymbolAddress((void**)&wh,  g_wh);
    cudaGetSymbolAddress((void**)&wl,  g_wl);

    cudaFuncSetAttribute(gemm_bf16x3, cudaFuncAttributeMaxDynamicSharedMemorySize, SMEM_GEMM);
    cudaFuncSetAttribute(attn_tc, cudaFuncAttributeMaxDynamicSharedMemorySize, SMEM_ATTN);

    // ---- splits: hs + all weights (Wq|Wk|Wv contiguous, then Wo) ----
    split_bf16<<<(HS_ELEMS / 4 + 255) / 256, 256>>>(hs, hsh, hsl, HS_ELEMS / 4);
    split_bf16<<<(HID_ * HID_ / 4 + 255) / 256, 256>>>(Wq, wh + WQ_OFF, wl + WQ_OFF, HID_ * HID_ / 4);
    split_bf16<<<(512 * HID_ / 4 + 255) / 256, 256>>>(Wk, wh + WK_OFF, wl + WK_OFF, 512 * HID_ / 4);
    split_bf16<<<(512 * HID_ / 4 + 255) / 256, 256>>>(Wv, wh + WV_OFF, wl + WV_OFF, 512 * HID_ / 4);
    split_bf16<<<(HID_ * HID_ / 4 + 255) / 256, 256>>>(Wo, wh + WO_OFF, wl + WO_OFF, HID_ * HID_ / 4);

    // ---- fused QKV projection (one launch, N=3072) ----
    gemm_bf16x3<<<dim3(QKVW / 128, 32), 256, SMEM_GEMM>>>(hsh, hsl, wh, wl, qkvp, QKVW);

    // ---- RoPE on q and k slices ----
    rope_kernel<<<B_SZ * S_LEN, NH * 32>>>(qkvp, cosp, sinp, QKVW, 0);
    rope_kernel<<<B_SZ * S_LEN, NKV * 32>>>(qkvp, cosp, sinp, QKVW, 2048);

    // ---- favor features ----
    init_stab_kernel<<<1, 32>>>(stabp);
    favor_xp<<<dim3(S_LEN / 32, NH, B_SZ), 256>>>(qkvp, proj, phiqp, nullptr, nullptr, NH, QKVW, 0);
    favor_xp<<<dim3(S_LEN / 32, NKV, B_SZ), 256>>>(qkvp, proj, phikp, sqkp, stabp, NKV, QKVW, 2048);
    favor_fin<<<(B_SZ * NKV * S_LEN) / 8, 256>>>(phikp, sqkp, stabp, B_SZ * NKV * S_LEN);

    // ---- chunked linear attention ----
    kv_chunk<<<dim3(NC, NKV, B_SZ), 256>>>(phikp, qkvp, kvp, kzp);
    cumsum_k<<<(B_SZ * NKV * (M_FEAT * D_HEAD + M_FEAT) + 255) / 256, 256>>>(kvp, kzp);
    attn_tc<<<dim3(NC, NH, B_SZ), 256, SMEM_ATTN>>>(phiqp, phikp, qkvp, kvp, kzp, attnp);

    // ---- output projection ----
    split_bf16<<<(HS_ELEMS / 4 + 255) / 256, 256>>>(attnp, ath, atl, HS_ELEMS / 4);
    gemm_bf16x3<<<dim3(16, 32), 256, SMEM_GEMM>>>(ath, atl, wh + WO_OFF, wl + WO_OFF, out, 2048);
}

// round 8
// speedup vs baseline: 1.4374x; 1.0051x over previous
#include <cuda_runtime.h>
#include <cuda_bf16.h>
#include <math.h>
#include <stdint.h>

#define B_SZ   2
#define S_LEN  2048
#define HID_   2048
#define NH     32
#define NKV    8
#define D_HEAD 64
#define M_FEAT 256
#define NC     16
#define CHUNK  128
#define QKVW   3072

// ---------------- scratch (device globals; no allocations allowed) ----------------
__device__ float g_qkv [(size_t)B_SZ * S_LEN * QKVW];
__device__ float g_xpk [(size_t)B_SZ * NKV * S_LEN * M_FEAT];   // k pre-exp xp
__device__ float g_sqk [B_SZ * NKV * S_LEN];
__device__ float g_stab[B_SZ * NKV];
__device__ float g_kv  [B_SZ * NKV * NC * M_FEAT * D_HEAD];
__device__ float g_kz  [B_SZ * NKV * NC * M_FEAT];

// bf16 phi (hi/lo) + activation/weight splits
#define PHIQ_E ((size_t)B_SZ * NH  * S_LEN * M_FEAT)
#define PHIK_E ((size_t)B_SZ * NKV * S_LEN * M_FEAT)
#define HS_ELEMS  (B_SZ * S_LEN * HID_)
#define W_ELEMS   (QKVW * HID_ + HID_ * HID_)
__device__ __align__(16) __nv_bfloat16 g_pqh[PHIQ_E];
__device__ __align__(16) __nv_bfloat16 g_pql[PHIQ_E];
__device__ __align__(16) __nv_bfloat16 g_pkh[PHIK_E];
__device__ __align__(16) __nv_bfloat16 g_pkl[PHIK_E];
__device__ __align__(16) __nv_bfloat16 g_hsh[HS_ELEMS];
__device__ __align__(16) __nv_bfloat16 g_hsl[HS_ELEMS];
__device__ __align__(16) __nv_bfloat16 g_ath[HS_ELEMS];
__device__ __align__(16) __nv_bfloat16 g_atl[HS_ELEMS];
__device__ __align__(16) __nv_bfloat16 g_wh [W_ELEMS];
__device__ __align__(16) __nv_bfloat16 g_wl [W_ELEMS];

#define WQ_OFF 0
#define WK_OFF (HID_ * HID_)
#define WV_OFF (WK_OFF + 512 * HID_)
#define WO_OFF (WV_OFF + 512 * HID_)

// =================== fp32 -> bf16 hi/lo split (elementwise, x4 vec) ================
__global__ void split_bf16(const float* __restrict__ x, __nv_bfloat16* __restrict__ h,
                           __nv_bfloat16* __restrict__ l, int n4)
{
    int i = blockIdx.x * blockDim.x + threadIdx.x;
    if (i >= n4) return;
    float4 v = ((const float4*)x)[i];
    __nv_bfloat16 h0 = __float2bfloat16(v.x), h1 = __float2bfloat16(v.y);
    __nv_bfloat16 h2 = __float2bfloat16(v.z), h3 = __float2bfloat16(v.w);
    __nv_bfloat162* hp = (__nv_bfloat162*)h;
    hp[2 * i]     = __nv_bfloat162(h0, h1);
    hp[2 * i + 1] = __nv_bfloat162(h2, h3);
    __nv_bfloat162* lp = (__nv_bfloat162*)l;
    lp[2 * i]     = __nv_bfloat162(__float2bfloat16(v.x - __bfloat162float(h0)),
                                   __float2bfloat16(v.y - __bfloat162float(h1)));
    lp[2 * i + 1] = __nv_bfloat162(__float2bfloat16(v.z - __bfloat162float(h2)),
                                   __float2bfloat16(v.w - __bfloat162float(h3)));
}

// ===================== shared helpers for tensor-core kernels ======================
__device__ __forceinline__ uint32_t smem_u32g(const void* p)
{
    uint32_t a;
    asm("{ .reg .u64 t; cvta.to.shared.u64 t, %1; cvt.u32.u64 %0, t; }" : "=r"(a) : "l"(p));
    return a;
}

#define LDSM4(r, a) \
    asm volatile("ldmatrix.sync.aligned.m8n8.x4.shared.b16 {%0,%1,%2,%3}, [%4];" \
                 : "=r"((r)[0]), "=r"((r)[1]), "=r"((r)[2]), "=r"((r)[3]) : "r"(a))

__device__ __forceinline__ void mma_bf16(float c[4], const uint32_t a[4], const uint32_t b[2])
{
    asm volatile("mma.sync.aligned.m16n8k16.row.col.f32.bf16.bf16.f32 "
                 "{%0,%1,%2,%3}, {%4,%5,%6,%7}, {%8,%9}, {%0,%1,%2,%3};"
                 : "+f"(c[0]), "+f"(c[1]), "+f"(c[2]), "+f"(c[3])
                 : "r"(a[0]), "r"(a[1]), "r"(a[2]), "r"(a[3]), "r"(b[0]), "r"(b[1]));
}

__device__ __forceinline__ void pack8(const float* f, uint4& hv, uint4& lv)
{
    uint32_t hw[4], lw[4];
#pragma unroll
    for (int e = 0; e < 4; e++) {
        __nv_bfloat16 h0 = __float2bfloat16(f[2 * e]);
        __nv_bfloat16 h1 = __float2bfloat16(f[2 * e + 1]);
        __nv_bfloat162 hp(h0, h1);
        hw[e] = *(uint32_t*)&hp;
        __nv_bfloat162 lp(__float2bfloat16(f[2 * e]     - __bfloat162float(h0)),
                          __float2bfloat16(f[2 * e + 1] - __bfloat162float(h1)));
        lw[e] = *(uint32_t*)&lp;
    }
    hv = make_uint4(hw[0], hw[1], hw[2], hw[3]);
    lv = make_uint4(lw[0], lw[1], lw[2], lw[3]);
}

// ======== bf16 3-pass split GEMM: ldmatrix + swizzled smem, m16n8k16 ===============
#define GK 2048
#define BK 32
#define NKT (GK / BK)
#define GBUF 32768
#define SMEM_GEMM (2 * GBUF)

__global__ __launch_bounds__(256, 1) void gemm_bf16x3(const __nv_bfloat16* __restrict__ Ah,
                                                      const __nv_bfloat16* __restrict__ Al,
                                                      const __nv_bfloat16* __restrict__ Bh,
                                                      const __nv_bfloat16* __restrict__ Bl,
                                                      float* __restrict__ C, int N)
{
    extern __shared__ char smc[];
    const uint32_t sb = smem_u32g(smc);
    const int tid  = threadIdx.x;
    const int warp = tid >> 5, lane = tid & 31;
    const int gid  = lane >> 2, tig = lane & 3;
    const int wm   = (warp & 1) * 64;
    const int wn   = (warp >> 1) * 32;
    const int rowA = blockIdx.y * 128;
    const int rowB = blockIdx.x * 128;

    const int st_row  = tid >> 2;
    const int st_slot = tid & 3;
    const uint32_t st_off0 = (uint32_t)(st_row * 64 + ((st_slot ^ ((st_row >> 1) & 3)) * 16));
    const int st_row1 = st_row + 64;
    const uint32_t st_off1 = (uint32_t)(st_row1 * 64 + ((st_slot ^ ((st_row1 >> 1) & 3)) * 16));

    const int swm   = ((lane & 7) >> 1) & 3;
    const int rlocA = (lane & 7) + (((lane >> 3) & 1) << 3);
    const int shA   = lane >> 4;
    const int rlocB = (lane & 7) + ((lane >> 4) << 3);
    const int shB   = (lane >> 3) & 1;

    float acc[4][4][4];
#pragma unroll
    for (int i = 0; i < 4; i++)
#pragma unroll
        for (int j = 0; j < 4; j++)
#pragma unroll
            for (int r = 0; r < 4; r++) acc[i][j][r] = 0.f;

    uint4 pAh[2], pAl[2], pBh[2], pBl[2];

    auto prefetch = [&](int kt) {
        const int kb = kt * BK;
        pAh[0] = *(const uint4*)(Ah + (size_t)(rowA + st_row)  * GK + kb + st_slot * 8);
        pAh[1] = *(const uint4*)(Ah + (size_t)(rowA + st_row1) * GK + kb + st_slot * 8);
        pAl[0] = *(const uint4*)(Al + (size_t)(rowA + st_row)  * GK + kb + st_slot * 8);
        pAl[1] = *(const uint4*)(Al + (size_t)(rowA + st_row1) * GK + kb + st_slot * 8);
        pBh[0] = *(const uint4*)(Bh + (size_t)(rowB + st_row)  * GK + kb + st_slot * 8);
        pBh[1] = *(const uint4*)(Bh + (size_t)(rowB + st_row1) * GK + kb + st_slot * 8);
        pBl[0] = *(const uint4*)(Bl + (size_t)(rowB + st_row)  * GK + kb + st_slot * 8);
        pBl[1] = *(const uint4*)(Bl + (size_t)(rowB + st_row1) * GK + kb + st_slot * 8);
    };
    auto commit = [&](int b) {
        char* buf = smc + b * GBUF;
        *(uint4*)(buf + st_off0)         = pAh[0];
        *(uint4*)(buf + st_off1)         = pAh[1];
        *(uint4*)(buf + 8192  + st_off0) = pAl[0];
        *(uint4*)(buf + 8192  + st_off1) = pAl[1];
        *(uint4*)(buf + 16384 + st_off0) = pBh[0];
        *(uint4*)(buf + 16384 + st_off1) = pBh[1];
        *(uint4*)(buf + 24576 + st_off0) = pBl[0];
        *(uint4*)(buf + 24576 + st_off1) = pBl[1];
    };

    prefetch(0);
    commit(0);
    __syncthreads();

    for (int kt = 0; kt < NKT; kt++) {
        const uint32_t base = sb + (kt & 1) * GBUF;
        if (kt + 1 < NKT) prefetch(kt + 1);

#pragma unroll
        for (int kb = 0; kb < 2; kb++) {
            uint32_t ah[4][4], al[4][4];
#pragma unroll
            for (int tm = 0; tm < 4; tm++) {
                const int r = wm + tm * 16 + rlocA;
                const uint32_t off = (uint32_t)(r * 64 + (((2 * kb + shA) ^ swm) * 16));
                LDSM4(ah[tm], base + off);
                LDSM4(al[tm], base + 8192 + off);
            }
            uint32_t bhf[2][4], blf[2][4];
#pragma unroll
            for (int p = 0; p < 2; p++) {
                const int r = wn + p * 16 + rlocB;
                const uint32_t off = (uint32_t)(r * 64 + (((2 * kb + shB) ^ swm) * 16));
                LDSM4(bhf[p], base + 16384 + off);
                LDSM4(blf[p], base + 24576 + off);
            }
#pragma unroll
            for (int tm = 0; tm < 4; tm++)
#pragma unroll
                for (int tn = 0; tn < 4; tn++) {
                    const uint32_t* bh2 = &bhf[tn >> 1][(tn & 1) * 2];
                    const uint32_t* bl2 = &blf[tn >> 1][(tn & 1) * 2];
                    mma_bf16(acc[tm][tn], ah[tm], bh2);
                    mma_bf16(acc[tm][tn], ah[tm], bl2);
                    mma_bf16(acc[tm][tn], al[tm], bh2);
                }
        }
        if (kt + 1 < NKT) commit((kt + 1) & 1);
        __syncthreads();
    }

#pragma unroll
    for (int tm = 0; tm < 4; tm++) {
        const size_t r0 = (size_t)rowA + wm + tm * 16 + gid;
#pragma unroll
        for (int tn = 0; tn < 4; tn++) {
            const int cn = rowB + wn + tn * 8 + tig * 2;
            *(float2*)(C + r0 * N + cn)       = make_float2(acc[tm][tn][0], acc[tm][tn][1]);
            *(float2*)(C + (r0 + 8) * N + cn) = make_float2(acc[tm][tn][2], acc[tm][tn][3]);
        }
    }
}

// ---------------- RoPE, in place on combined buffer --------------------------------
__global__ void rope_kernel(float* __restrict__ x, const float* __restrict__ cosp,
                            const float* __restrict__ sinp, int stride, int coloff)
{
    const int row = blockIdx.x;
    const int h = threadIdx.x >> 5, p = threadIdx.x & 31;
    const float c1 = cosp[row * 64 + p],      s1 = sinp[row * 64 + p];
    const float c2 = cosp[row * 64 + 32 + p], s2 = sinp[row * 64 + 32 + p];
    float* xr = x + (size_t)row * stride + coloff + h * 64;
    const float x1 = xr[p], x2 = xr[p + 32];
    xr[p]      = x1 * c1 - x2 * s1;
    xr[p + 32] = x2 * c2 + x1 * s2;
}

__device__ void atomicMaxFloat(float* addr, float val)
{
    int* ia = (int*)addr;
    int old = *ia;
    while (__int_as_float(old) < val) {
        int assumed = old;
        old = atomicCAS(ia, assumed, __float_as_int(val));
        if (old == assumed) break;
    }
}

__global__ void init_stab_kernel(float* stab)
{
    if (threadIdx.x < B_SZ * NKV) stab[threadIdx.x] = -3.4e38f;
}

// ---------------- favor xp -----------------------------------------------------
// q path (stab==null): fused exp, writes bf16 hi/lo phi directly.
// k path: writes fp32 xp (+ sq, head max).
__global__ __launch_bounds__(256) void favor_xp(const float* __restrict__ x,
                                                const float* __restrict__ proj,
                                                float* __restrict__ xp,
                                                __nv_bfloat16* __restrict__ ph,
                                                __nv_bfloat16* __restrict__ pl,
                                                float* __restrict__ sq,
                                                float* __restrict__ stab,
                                                int nheads, int xstride, int xcoloff)
{
    __shared__ float As[32 * 68];
    __shared__ float Bs[16][256];
    __shared__ float red[256];
    __shared__ float sqsh[32];
    const float DN = 0.35355339059327373f;
    const int s0 = blockIdx.x * 32, h = blockIdx.y, b = blockIdx.z;
    const int tid = threadIdx.x;

#pragma unroll
    for (int r = 0; r < 2; r++) {
        int l = tid + r * 256;
        int tok = l >> 4, q4 = (l & 15) << 2;
        float4 vv = *(const float4*)(x + (size_t)(b * S_LEN + s0 + tok) * xstride + xcoloff + h * 64 + q4);
        As[tok * 68 + q4 + 0] = vv.x * DN;
        As[tok * 68 + q4 + 1] = vv.y * DN;
        As[tok * 68 + q4 + 2] = vv.z * DN;
        As[tok * 68 + q4 + 3] = vv.w * DN;
    }
    __syncthreads();
    if (tid < 32) {
        float ssum = 0.f;
#pragma unroll
        for (int d = 0; d < 64; d++) { float vv = As[tid * 68 + d]; ssum += vv * vv; }
        sqsh[tid] = 0.5f * ssum;
        if (sq) sq[((size_t)(b * nheads + h)) * S_LEN + s0 + tid] = 0.5f * ssum;
    }

    const int tg = tid >> 5, mg = tid & 31;
    float acc[4][8];
#pragma unroll
    for (int i = 0; i < 4; i++)
#pragma unroll
        for (int j = 0; j < 8; j++) acc[i][j] = 0.f;

    for (int k0 = 0; k0 < 64; k0 += 16) {
#pragma unroll
        for (int j = 0; j < 4; j++) {
            float4 p = *(const float4*)(proj + tid * 64 + k0 + j * 4);
            Bs[j * 4 + 0][tid] = p.x; Bs[j * 4 + 1][tid] = p.y;
            Bs[j * 4 + 2][tid] = p.z; Bs[j * 4 + 3][tid] = p.w;
        }
        __syncthreads();
#pragma unroll
        for (int kk = 0; kk < 16; kk++) {
            float a[4];
#pragma unroll
            for (int i = 0; i < 4; i++) a[i] = As[(tg * 4 + i) * 68 + k0 + kk];
            float bb[8];
            *(float4*)&bb[0] = *(const float4*)&Bs[kk][mg * 8];
            *(float4*)&bb[4] = *(const float4*)&Bs[kk][mg * 8 + 4];
#pragma unroll
            for (int i = 0; i < 4; i++)
#pragma unroll
                for (int j = 0; j < 8; j++) acc[i][j] += a[i] * bb[j];
        }
        __syncthreads();
    }

    const size_t rowbase = (size_t)(b * nheads + h) * S_LEN + s0;
    if (stab == nullptr) {
        // q path: row max -> exp -> split to bf16 hi/lo
#pragma unroll
        for (int i = 0; i < 4; i++) {
            float m = acc[i][0];
#pragma unroll
            for (int j = 1; j < 8; j++) m = fmaxf(m, acc[i][j]);
#pragma unroll
            for (int o = 16; o > 0; o >>= 1) m = fmaxf(m, __shfl_xor_sync(0xffffffffu, m, o));
            const float sv = sqsh[tg * 4 + i];
#pragma unroll
            for (int j = 0; j < 8; j++)
                acc[i][j] = (expf(acc[i][j] - sv - m) + 1e-6f) * 0.0625f;
            uint4 hv, lv;
            pack8(acc[i], hv, lv);
            *(uint4*)(ph + (rowbase + tg * 4 + i) * M_FEAT + mg * 8) = hv;
            *(uint4*)(pl + (rowbase + tg * 4 + i) * M_FEAT + mg * 8) = lv;
        }
    } else {
        float mx = -3.4e38f;
#pragma unroll
        for (int i = 0; i < 4; i++) {
            *(float4*)(xp + (rowbase + tg * 4 + i) * M_FEAT + mg * 8) =
                make_float4(acc[i][0], acc[i][1], acc[i][2], acc[i][3]);
            *(float4*)(xp + (rowbase + tg * 4 + i) * M_FEAT + mg * 8 + 4) =
                make_float4(acc[i][4], acc[i][5], acc[i][6], acc[i][7]);
#pragma unroll
            for (int j = 0; j < 8; j++) mx = fmaxf(mx, acc[i][j]);
        }
        red[tid] = mx;
        __syncthreads();
        for (int st = 128; st > 0; st >>= 1) {
            if (tid < st) red[tid] = fmaxf(red[tid], red[tid + st]);
            __syncthreads();
        }
        if (tid == 0) atomicMaxFloat(&stab[b * nheads + h], red[0]);
    }
}

// ---------------- k finalize: exp + split to bf16 hi/lo ----------------------------
__global__ void favor_fin(const float* __restrict__ xp, const float* __restrict__ sq,
                          const float* __restrict__ stab,
                          __nv_bfloat16* __restrict__ ph, __nv_bfloat16* __restrict__ pl,
                          int nrows)
{
    const int warp = (blockIdx.x * blockDim.x + threadIdx.x) >> 5;
    const int lane = threadIdx.x & 31;
    if (warp >= nrows) return;
    const float* row = xp + (size_t)warp * M_FEAT;
    const float mx  = stab[warp / S_LEN];
    const float sqv = sq[warp];
    float f[8];
    *(float4*)&f[0] = *(const float4*)(row + lane * 8);
    *(float4*)&f[4] = *(const float4*)(row + lane * 8 + 4);
#pragma unroll
    for (int k = 0; k < 8; k++) f[k] = (expf(f[k] - sqv - mx) + 1e-6f) * 0.0625f;
    uint4 hv, lv;
    pack8(f, hv, lv);
    *(uint4*)(ph + (size_t)warp * M_FEAT + lane * 8) = hv;
    *(uint4*)(pl + (size_t)warp * M_FEAT + lane * 8) = lv;
}

// ---------------- per-chunk kv (M x D) and kz (M). grid (NC, NKV, B) ---------------
__global__ __launch_bounds__(256) void kv_chunk(const __nv_bfloat16* __restrict__ pkh,
                                                const __nv_bfloat16* __restrict__ pkl,
                                                const float* __restrict__ qkv,
                                                float* __restrict__ kv,
                                                float* __restrict__ kz)
{
    __shared__ float ps[16][256];
    __shared__ float vs[16][64];
    const int c = blockIdx.x, h = blockIdx.y, b = blockIdx.z;
    const int tid = threadIdx.x;
    float acc[64];
#pragma unroll
    for (int d = 0; d < 64; d++) acc[d] = 0.f;
    float accz = 0.f;
    const size_t prow = (size_t)(b * NKV + h) * S_LEN + c * CHUNK;
    const size_t vrow = (size_t)b * S_LEN + c * CHUNK;

    for (int i0 = 0; i0 < CHUNK; i0 += 16) {
#pragma unroll
        for (int ii = 0; ii < 16; ii++) {
            const size_t idx = (prow + i0 + ii) * M_FEAT + tid;
            ps[ii][tid] = __bfloat162float(pkh[idx]) + __bfloat162float(pkl[idx]);
        }
#pragma unroll
        for (int j = 0; j < 4; j++) {
            int l = tid + j * 256;
            int ii = l >> 6, d = l & 63;
            vs[ii][d] = qkv[(vrow + i0 + ii) * QKVW + 2560 + h * 64 + d];
        }
        __syncthreads();
#pragma unroll
        for (int ii = 0; ii < 16; ii++) {
            float a = ps[ii][tid];
            accz += a;
#pragma unroll
            for (int d4 = 0; d4 < 64; d4 += 4) {
                float4 vv = *(const float4*)&vs[ii][d4];
                acc[d4 + 0] += a * vv.x; acc[d4 + 1] += a * vv.y;
                acc[d4 + 2] += a * vv.z; acc[d4 + 3] += a * vv.w;
            }
        }
        __syncthreads();
    }
    const size_t ob = (((size_t)(b * NKV + h) * NC + c) * M_FEAT + tid) * D_HEAD;
#pragma unroll
    for (int d4 = 0; d4 < 64; d4 += 4)
        *(float4*)(kv + ob + d4) = make_float4(acc[d4], acc[d4 + 1], acc[d4 + 2], acc[d4 + 3]);
    kz[((size_t)(b * NKV + h) * NC + c) * M_FEAT + tid] = accz;
}

// ---------------- exclusive prefix over chunk axis, in place ----------------------
__global__ void cumsum_k(float* __restrict__ kv, float* __restrict__ kz)
{
    const int tid = blockIdx.x * blockDim.x + threadIdx.x;
    const int KVSZ = M_FEAT * D_HEAD;
    if (tid < B_SZ * NKV * KVSZ) {
        int bh = tid / KVSZ, md = tid % KVSZ;
        float run = 0.f;
        for (int c = 0; c < NC; c++) {
            size_t idx = ((size_t)bh * NC + c) * KVSZ + md;
            float t = kv[idx]; kv[idx] = run; run += t;
        }
    } else {
        int t2 = tid - B_SZ * NKV * KVSZ;
        if (t2 < B_SZ * NKV * M_FEAT) {
            int bh = t2 / M_FEAT, m = t2 % M_FEAT;
            float run = 0.f;
            for (int c = 0; c < NC; c++) {
                size_t idx = ((size_t)bh * NC + c) * M_FEAT + m;
                float tz = kz[idx]; kz[idx] = run; run += tz;
            }
        }
    }
}

// ============ tensor-core chunked causal linear attention. grid (NC, NH, B) ========
#define SPITCH 132
#define SMEM_ATTN (128 * SPITCH * 4 + 4 * 8192 + 512)

__global__ __launch_bounds__(256, 1) void attn_tc(
    const __nv_bfloat16* __restrict__ pqh, const __nv_bfloat16* __restrict__ pql,
    const __nv_bfloat16* __restrict__ pkh, const __nv_bfloat16* __restrict__ pkl,
    const float* __restrict__ qkv, const float* __restrict__ kvpre,
    const float* __restrict__ kzpre,
    __nv_bfloat16* __restrict__ ath, __nv_bfloat16* __restrict__ atl)
{
    extern __shared__ float sm[];
    float* Ss = sm;
    char* Ah = (char*)(sm + 128 * SPITCH);
    char* Al = Ah + 8192;
    char* Bh = Al + 8192;
    char* Bl = Bh + 8192;
    float* Zs = (float*)(Bl + 8192);

    const uint32_t sbAh = smem_u32g(Ah), sbAl = smem_u32g(Al);
    const uint32_t sbBh = smem_u32g(Bh), sbBl = smem_u32g(Bl);

    const int c = blockIdx.x, h = blockIdx.y, b = blockIdx.z;
    const int kvh = h >> 2;
    const int tid = threadIdx.x;
    const int warp = tid >> 5, lane = tid & 31;
    const int gid = lane >> 2, tig = lane & 3;

    const size_t qbase  = (size_t)(b * NH + h) * S_LEN + c * CHUNK;
    const size_t kbase  = (size_t)(b * NKV + kvh) * S_LEN + c * CHUNK;
    const size_t vrow0  = (size_t)b * S_LEN + c * CHUNK;
    const size_t kvbase = ((size_t)(b * NKV + kvh) * NC + c) * (size_t)(M_FEAT * D_HEAD);
    const size_t kzbase = ((size_t)(b * NKV + kvh) * NC + c) * M_FEAT;

    const int strow = tid & 127;
    const int s0 = tid >> 7;

    const int swm   = ((lane & 7) >> 1) & 3;
    const int rlocA = (lane & 7) + (((lane >> 3) & 1) << 3);
    const int shA   = lane >> 4;
    const int rlocB = (lane & 7) + ((lane >> 4) << 3);
    const int shB   = (lane >> 3) & 1;

    // ======================= Phase 1: scores =======================
    {
        const int wm = (warp & 1) * 64, wn = (warp >> 1) * 32;
        float acc[4][4][4];
#pragma unroll
        for (int i = 0; i < 4; i++)
#pragma unroll
            for (int j = 0; j < 4; j++)
#pragma unroll
                for (int r = 0; r < 4; r++) acc[i][j][r] = 0.f;

        for (int m0 = 0; m0 < M_FEAT; m0 += 32) {
#pragma unroll
            for (int si = 0; si < 2; si++) {
                const int s = s0 + si * 2;
                const uint32_t off = (uint32_t)(strow * 64 + ((s ^ ((strow >> 1) & 3)) * 16));
                const size_t ia = (qbase + strow) * M_FEAT + m0 + s * 8;
                *(uint4*)(Ah + off) = *(const uint4*)(pqh + ia);
                *(uint4*)(Al + off) = *(const uint4*)(pql + ia);
                const size_t ib = (kbase + strow) * M_FEAT + m0 + s * 8;
                *(uint4*)(Bh + off) = *(const uint4*)(pkh + ib);
                *(uint4*)(Bl + off) = *(const uint4*)(pkl + ib);
            }
            __syncthreads();
#pragma unroll
            for (int kb = 0; kb < 2; kb++) {
                uint32_t ah[4][4], al[4][4];
#pragma unroll
                for (int tm = 0; tm < 4; tm++) {
                    const int r = wm + tm * 16 + rlocA;
                    const uint32_t off = (uint32_t)(r * 64 + (((2 * kb + shA) ^ swm) * 16));
                    LDSM4(ah[tm], sbAh + off);
                    LDSM4(al[tm], sbAl + off);
                }
                uint32_t bhf[2][4], blf[2][4];
#pragma unroll
                for (int p = 0; p < 2; p++) {
                    const int r = wn + p * 16 + rlocB;
                    const uint32_t off = (uint32_t)(r * 64 + (((2 * kb + shB) ^ swm) * 16));
                    LDSM4(bhf[p], sbBh + off);
                    LDSM4(blf[p], sbBl + off);
                }
#pragma unroll
                for (int tm = 0; tm < 4; tm++)
#pragma unroll
                    for (int tn = 0; tn < 4; tn++) {
                        const uint32_t* bh2 = &bhf[tn >> 1][(tn & 1) * 2];
                        const uint32_t* bl2 = &blf[tn >> 1][(tn & 1) * 2];
                        mma_bf16(acc[tm][tn], ah[tm], bh2);
                        mma_bf16(acc[tm][tn], ah[tm], bl2);
                        mma_bf16(acc[tm][tn], al[tm], bh2);
                    }
            }
            __syncthreads();
        }
#pragma unroll
        for (int tm = 0; tm < 4; tm++) {
            const int r0 = wm + tm * 16 + gid;
            const int r1 = r0 + 8;
#pragma unroll
            for (int tn = 0; tn < 4; tn++) {
                const int col = wn + tn * 8 + tig * 2;
                Ss[r0 * SPITCH + col]     = (col     <= r0) ? acc[tm][tn][0] : 0.f;
                Ss[r0 * SPITCH + col + 1] = (col + 1 <= r0) ? acc[tm][tn][1] : 0.f;
                Ss[r1 * SPITCH + col]     = (col     <= r1) ? acc[tm][tn][2] : 0.f;
                Ss[r1 * SPITCH + col + 1] = (col + 1 <= r1) ? acc[tm][tn][3] : 0.f;
            }
        }
    }
    __syncthreads();

    // ======================= Phase 2: inter+intra (+z col 64) =======================
    const int wm2 = (warp & 3) * 32, wn2 = (warp >> 2) * 40;
    float acc2[2][5][4];
#pragma unroll
    for (int i = 0; i < 2; i++)
#pragma unroll
        for (int j = 0; j < 5; j++)
#pragma unroll
            for (int r = 0; r < 4; r++) acc2[i][j][r] = 0.f;

    for (int cc = 0; cc < 12; cc++) {
#pragma unroll
        for (int si = 0; si < 2; si++) {
            const int s = s0 + si * 2;
            const uint32_t off = (uint32_t)(strow * 64 + ((s ^ ((strow >> 1) & 3)) * 16));
            if (cc < 8) {
                const size_t ia = (qbase + strow) * M_FEAT + cc * 32 + s * 8;
                *(uint4*)(Ah + off) = *(const uint4*)(pqh + ia);
                *(uint4*)(Al + off) = *(const uint4*)(pql + ia);
            } else {
                float f[8];
                const float* pa = Ss + strow * SPITCH + (cc - 8) * 32 + s * 8;
                *(float4*)&f[0] = *(const float4*)pa;
                *(float4*)&f[4] = *(const float4*)(pa + 4);
                uint4 hv, lv;
                pack8(f, hv, lv);
                *(uint4*)(Ah + off) = hv;
                *(uint4*)(Al + off) = lv;
            }

            if (strow < 96) {
                float g[8];
                if (strow < 64) {
                    if (cc < 8) {
#pragma unroll
                        for (int e = 0; e < 8; e++)
                            g[e] = kvpre[kvbase + (size_t)(cc * 32 + s * 8 + e) * 64 + strow];
                    } else {
#pragma unroll
                        for (int e = 0; e < 8; e++)
                            g[e] = qkv[(vrow0 + (cc - 8) * 32 + s * 8 + e) * QKVW + 2560 + kvh * 64 + strow];
                    }
                } else if (strow == 64) {
                    if (cc < 8) {
#pragma unroll
                        for (int e = 0; e < 8; e++)
                            g[e] = kzpre[kzbase + cc * 32 + s * 8 + e];
                    } else {
#pragma unroll
                        for (int e = 0; e < 8; e++) g[e] = 1.f;
                    }
                } else {
#pragma unroll
                    for (int e = 0; e < 8; e++) g[e] = 0.f;
                }
                uint4 hv, lv;
                pack8(g, hv, lv);
                *(uint4*)(Bh + off) = hv;
                *(uint4*)(Bl + off) = lv;
            }
        }
        __syncthreads();
#pragma unroll
        for (int kb = 0; kb < 2; kb++) {
            uint32_t ah2[2][4], al2[2][4], bh2[3][4], bl2[3][4];
#pragma unroll
            for (int tm = 0; tm < 2; tm++) {
                const int r = wm2 + tm * 16 + rlocA;
                const uint32_t off = (uint32_t)(r * 64 + (((2 * kb + shA) ^ swm) * 16));
                LDSM4(ah2[tm], sbAh + off);
                LDSM4(al2[tm], sbAl + off);
            }
#pragma unroll
            for (int p = 0; p < 3; p++) {
                const int r = wn2 + p * 16 + rlocB;
                const uint32_t off = (uint32_t)(r * 64 + (((2 * kb + shB) ^ swm) * 16));
                LDSM4(bh2[p], sbBh + off);
                LDSM4(bl2[p], sbBl + off);
            }
#pragma unroll
            for (int tm = 0; tm < 2; tm++)
#pragma unroll
                for (int tn = 0; tn < 5; tn++) {
                    const uint32_t* bh_ = &bh2[tn >> 1][(tn & 1) * 2];
                    const uint32_t* bl_ = &bl2[tn >> 1][(tn & 1) * 2];
                    mma_bf16(acc2[tm][tn], ah2[tm], bh_);
                    mma_bf16(acc2[tm][tn], ah2[tm], bl_);
                    mma_bf16(acc2[tm][tn], al2[tm], bh_);
                }
        }
        __syncthreads();
    }

    if ((warp >> 2) == 1 && tig == 0) {
#pragma unroll
        for (int tm = 0; tm < 2; tm++) {
            const int r = wm2 + tm * 16 + gid;
            Zs[r]     = acc2[tm][3][0];
            Zs[r + 8] = acc2[tm][3][2];
        }
    }
    __syncthreads();

    // epilogue: divide + write bf16 hi/lo activations directly
#pragma unroll
    for (int tm = 0; tm < 2; tm++) {
        const int r = wm2 + tm * 16 + gid;
        const float d0 = 1.f / (Zs[r] + 1e-6f);
        const float d1 = 1.f / (Zs[r + 8] + 1e-6f);
#pragma unroll
        for (int tn = 0; tn < 5; tn++) {
            const int col = wn2 + tn * 8 + tig * 2;
            if (col < 64) {
                const size_t ro = ((size_t)b * S_LEN + c * CHUNK + r) * (NH * D_HEAD) + h * 64 + col;
                const size_t ro8 = ro + 8 * (NH * D_HEAD);
                float o0 = acc2[tm][tn][0] * d0, o1 = acc2[tm][tn][1] * d0;
                float o2 = acc2[tm][tn][2] * d1, o3 = acc2[tm][tn][3] * d1;
                __nv_bfloat16 h0 = __float2bfloat16(o0), h1 = __float2bfloat16(o1);
                __nv_bfloat16 h2 = __float2bfloat16(o2), h3 = __float2bfloat16(o3);
                *(__nv_bfloat162*)(ath + ro)  = __nv_bfloat162(h0, h1);
                *(__nv_bfloat162*)(ath + ro8) = __nv_bfloat162(h2, h3);
                *(__nv_bfloat162*)(atl + ro)  =
                    __nv_bfloat162(__float2bfloat16(o0 - __bfloat162float(h0)),
                                   __float2bfloat16(o1 - __bfloat162float(h1)));
                *(__nv_bfloat162*)(atl + ro8) =
                    __nv_bfloat162(__float2bfloat16(o2 - __bfloat162float(h2)),
                                   __float2bfloat16(o3 - __bfloat162float(h3)));
            }
        }
    }
}

// ----------------------------------- launch ---------------------------------------
extern "C" void kernel_launch(void* const* d_in, const int* in_sizes, int n_in,
                              void* d_out, int out_size)
{
    const float* hs   = (const float*)d_in[0];
    const float* cosp = (const float*)d_in[1];
    const float* sinp = (const float*)d_in[2];
    const float* Wq   = (const float*)d_in[3];
    const float* Wk   = (const float*)d_in[4];
    const float* Wv   = (const float*)d_in[5];
    const float* Wo   = (const float*)d_in[6];
    const float* proj = (const float*)d_in[7];
    float* out = (float*)d_out;

    float *qkvp, *xpkp, *sqkp, *stabp, *kvp, *kzp;
    cudaGetSymbolAddress((void**)&qkvp,  g_qkv);
    cudaGetSymbolAddress((void**)&xpkp,  g_xpk);
    cudaGetSymbolAddress((void**)&sqkp,  g_sqk);
    cudaGetSymbolAddress((void**)&stabp, g_stab);
    cudaGetSymbolAddress((void**)&kvp,   g_kv);
    cudaGetSymbolAddress((void**)&kzp,   g_kz);

    __nv_bfloat16 *pqh, *pql, *pkh, *pkl, *hsh, *hsl, *ath, *atl, *wh, *wl;
    cudaGetSymbolAddress((void**)&pqh, g_pqh);
    cudaGetSymbolAddress((void**)&pql, g_pql);
    cudaGetSymbolAddress((void**)&pkh, g_pkh);
    cudaGetSymbolAddress((void**)&pkl, g_pkl);
    cudaGetSymbolAddress((void**)&hsh, g_hsh);
    cudaGetSymbolAddress((void**)&hsl, g_hsl);
    cudaGetSymbolAddress((void**)&ath, g_ath);
    cudaGetSymbolAddress((void**)&atl, g_atl);
    cudaGetSymbolAddress((void**)&wh,  g_wh);
    cudaGetSymbolAddress((void**)&wl,  g_wl);

    cudaFuncSetAttribute(gemm_bf16x3, cudaFuncAttributeMaxDynamicSharedMemorySize, SMEM_GEMM);
    cudaFuncSetAttribute(attn_tc, cudaFuncAttributeMaxDynamicSharedMemorySize, SMEM_ATTN);

    // ---- splits: hs + all weights ----
    split_bf16<<<(HS_ELEMS / 4 + 255) / 256, 256>>>(hs, hsh, hsl, HS_ELEMS / 4);
    split_bf16<<<(HID_ * HID_ / 4 + 255) / 256, 256>>>(Wq, wh + WQ_OFF, wl + WQ_OFF, HID_ * HID_ / 4);
    split_bf16<<<(512 * HID_ / 4 + 255) / 256, 256>>>(Wk, wh + WK_OFF, wl + WK_OFF, 512 * HID_ / 4);
    split_bf16<<<(512 * HID_ / 4 + 255) / 256, 256>>>(Wv, wh + WV_OFF, wl + WV_OFF, 512 * HID_ / 4);
    split_bf16<<<(HID_ * HID_ / 4 + 255) / 256, 256>>>(Wo, wh + WO_OFF, wl + WO_OFF, HID_ * HID_ / 4);

    // ---- fused QKV projection ----
    gemm_bf16x3<<<dim3(QKVW / 128, 32), 256, SMEM_GEMM>>>(hsh, hsl, wh, wl, qkvp, QKVW);

    // ---- RoPE ----
    rope_kernel<<<B_SZ * S_LEN, NH * 32>>>(qkvp, cosp, sinp, QKVW, 0);
    rope_kernel<<<B_SZ * S_LEN, NKV * 32>>>(qkvp, cosp, sinp, QKVW, 2048);

    // ---- favor features ----
    init_stab_kernel<<<1, 32>>>(stabp);
    favor_xp<<<dim3(S_LEN / 32, NH, B_SZ), 256>>>(qkvp, proj, nullptr, pqh, pql, nullptr, nullptr, NH, QKVW, 0);
    favor_xp<<<dim3(S_LEN / 32, NKV, B_SZ), 256>>>(qkvp, proj, xpkp, nullptr, nullptr, sqkp, stabp, NKV, QKVW, 2048);
    favor_fin<<<(B_SZ * NKV * S_LEN) / 8, 256>>>(xpkp, sqkp, stabp, pkh, pkl, B_SZ * NKV * S_LEN);

    // ---- chunked linear attention ----
    kv_chunk<<<dim3(NC, NKV, B_SZ), 256>>>(pkh, pkl, qkvp, kvp, kzp);
    cumsum_k<<<(B_SZ * NKV * (M_FEAT * D_HEAD + M_FEAT) + 255) / 256, 256>>>(kvp, kzp);
    attn_tc<<<dim3(NC, NH, B_SZ), 256, SMEM_ATTN>>>(pqh, pql, pkh, pkl, qkvp, kvp, kzp, ath, atl);

    // ---- output projection (consumes bf16 activations directly) ----
    gemm_bf16x3<<<dim3(16, 32), 256, SMEM_GEMM>>>(ath, atl, wh + WO_OFF, wl + WO_OFF, out, 2048);
}